// round 8
// baseline (speedup 1.0000x reference)
#include <cuda_runtime.h>
#include <cuda_bf16.h>
#include <stdint.h>

#define Bb 4
#define Nn 2048
#define Mm 2048
#define Cc 512
#define Hh 8
#define DHd 64
#define LOG2E 1.4426950408889634f

// ---------------- static scratch (no allocations allowed) ----------------
__device__ __nv_bfloat16 g_qhi[Bb*Hh*Nn*DHd];   // [bh][n][dh], pre-scaled by 1/8
__device__ __nv_bfloat16 g_qlo[Bb*Hh*Nn*DHd];
__device__ __nv_bfloat16 g_khi[Bb*Hh*Mm*DHd];   // [bh][m][dh], pre-scaled by kw*log2e
__device__ __nv_bfloat16 g_klo[Bb*Hh*Mm*DHd];
__device__ __nv_bfloat16 g_vhi[Bb*Hh*DHd*Mm];   // TRANSPOSED: [bh][dh][m]
__device__ __nv_bfloat16 g_vlo[Bb*Hh*DHd*Mm];
__device__ float        g_rs4[4][Bb*Hh*Nn];     // partial rowsums per m-quarter

// ---------------- helpers ----------------
__device__ __forceinline__ void mma_bf16(float c[4], const uint32_t a[4], const uint32_t b[2]) {
    asm volatile(
        "mma.sync.aligned.m16n8k16.row.col.f32.bf16.bf16.f32 "
        "{%0,%1,%2,%3}, {%4,%5,%6,%7}, {%8,%9}, {%0,%1,%2,%3};\n"
        : "+f"(c[0]), "+f"(c[1]), "+f"(c[2]), "+f"(c[3])
        : "r"(a[0]), "r"(a[1]), "r"(a[2]), "r"(a[3]), "r"(b[0]), "r"(b[1]));
}

__device__ __forceinline__ void split2(float x, __nv_bfloat16 &hi, __nv_bfloat16 &lo) {
    hi = __float2bfloat16_rn(x);
    lo = __float2bfloat16_rn(x - __bfloat162float(hi));
}

__device__ __forceinline__ uint32_t pk2(__nv_bfloat16 a, __nv_bfloat16 b) {
    return (uint32_t)__bfloat16_as_ushort(a) | ((uint32_t)__bfloat16_as_ushort(b) << 16);
}

// guaranteed MUFU.EX2 (ftz flushes 2^-127 to 0 for masked lanes)
__device__ __forceinline__ float ex2f(float x) {
    float r;
    asm("ex2.approx.ftz.f32 %0, %1;" : "=f"(r) : "f"(x));
    return r;
}

// ---- packed f32x2 helpers for the polynomial exp2 path ----
__device__ __forceinline__ uint64_t f2pk(float lo, float hi) {
    uint64_t r; asm("mov.b64 %0, {%1, %2};" : "=l"(r) : "f"(lo), "f"(hi)); return r;
}
__device__ __forceinline__ void f2un(uint64_t v, float &lo, float &hi) {
    asm("mov.b64 {%0, %1}, %2;" : "=f"(lo), "=f"(hi) : "l"(v));
}
__device__ __forceinline__ uint64_t fma2(uint64_t a, uint64_t b, uint64_t c) {
    uint64_t d; asm("fma.rn.f32x2 %0, %1, %2, %3;" : "=l"(d) : "l"(a), "l"(b), "l"(c)); return d;
}
__device__ __forceinline__ uint64_t add2(uint64_t a, uint64_t b) {
    uint64_t d; asm("add.rn.f32x2 %0, %1, %2;" : "=l"(d) : "l"(a), "l"(b)); return d;
}

// exp2 of (s*fa + fb) for a pair, FMA-pipe only. Masked (fa=0, fb=-127) -> exact 0.
__device__ __forceinline__ void exp2_pair(float s0, float s1, uint64_t fa2, uint64_t fb2,
                                          float &r0, float &r1) {
    const uint64_t MAG  = f2pk( 12582912.0f,  12582912.0f);   // 1.5*2^23
    const uint64_t NMAG = f2pk(-12582912.0f, -12582912.0f);
    const uint64_t NONE = f2pk(-1.0f, -1.0f);
    const uint64_t C4 = f2pk(0.0096181291f, 0.0096181291f);
    const uint64_t C3 = f2pk(0.0555041087f, 0.0555041087f);
    const uint64_t C2 = f2pk(0.2402265070f, 0.2402265070f);
    const uint64_t C1 = f2pk(0.6931471806f, 0.6931471806f);
    const uint64_t C0 = f2pk(1.0f, 1.0f);
    uint64_t sc2 = f2pk(s0, s1);
    uint64_t x2 = fma2(sc2, fa2, fb2);
    uint64_t y2 = add2(x2, MAG);          // bits: 0x4B400000 + n
    uint64_t n2 = add2(y2, NMAG);         // n as float
    uint64_t f2 = fma2(n2, NONE, x2);     // f = x - n, f in [-0.5, 0.5]
    uint64_t t2 = fma2(C4, f2, C3);
    t2 = fma2(t2, f2, C2);
    t2 = fma2(t2, f2, C1);
    t2 = fma2(t2, f2, C0);
    float yl, yh, tl, th;
    f2un(y2, yl, yh); f2un(t2, tl, th);
    int i0 = __float_as_int(tl) + (__float_as_int(yl) << 23);
    int i1 = __float_as_int(th) + (__float_as_int(yh) << 23);
    r0 = __int_as_float(i0);
    r1 = __int_as_float(i1);
}

// ---------------- K1: fused projections (X@W + b), bf16-split mma ----------------
// grid: (64, 8, 3)  block: 256
__global__ __launch_bounds__(256) void proj_kernel(
    const float* __restrict__ xq, const float* __restrict__ xk, const float* __restrict__ xv,
    const float* __restrict__ Wq, const float* __restrict__ bq,
    const float* __restrict__ Wk, const float* __restrict__ bk,
    const float* __restrict__ Wv, const float* __restrict__ bv,
    const float* __restrict__ kw)
{
    const float* X; const float* W; const float* bias;
    __nv_bfloat16 *Ohi, *Olo;
    int z = blockIdx.z;
    if (z == 0)      { X = xq; W = Wq; bias = bq; Ohi = g_qhi; Olo = g_qlo; }
    else if (z == 1) { X = xk; W = Wk; bias = bk; Ohi = g_khi; Olo = g_klo; }
    else             { X = xv; W = Wv; bias = bv; Ohi = g_vhi; Olo = g_vlo; }

    __shared__ __nv_bfloat16 Ahi[128][40], Alo[128][40];   // [row][k], k-chunk 32, pad 8
    __shared__ __nv_bfloat16 Bshi[64][40], Bslo[64][40];   // [col][k] transposed

    int tid = threadIdx.x, lane = tid & 31, warp = tid >> 5;
    int row0 = blockIdx.x * 128;
    int col0 = blockIdx.y * 64;
    int wr = (warp >> 1) * 32, wc = (warp & 1) * 32;
    int qr = lane >> 2, qc2 = (lane & 3) * 2;

    float acc[2][4][4];
#pragma unroll
    for (int m = 0; m < 2; m++)
#pragma unroll
        for (int n = 0; n < 4; n++)
#pragma unroll
            for (int e = 0; e < 4; e++) acc[m][n][e] = 0.0f;

    for (int kc = 0; kc < Cc; kc += 32) {
#pragma unroll
        for (int i = tid; i < 128*8; i += 256) {
            int r = i >> 3, c4 = (i & 7) * 4;
            float4 v = *(const float4*)&X[(size_t)(row0 + r)*Cc + kc + c4];
            __nv_bfloat16 h0,l0,h1,l1,h2,l2,h3,l3;
            split2(v.x, h0, l0); split2(v.y, h1, l1);
            split2(v.z, h2, l2); split2(v.w, h3, l3);
            uint2 th; th.x = pk2(h0,h1); th.y = pk2(h2,h3);
            uint2 tl; tl.x = pk2(l0,l1); tl.y = pk2(l2,l3);
            *(uint2*)&Ahi[r][c4] = th;
            *(uint2*)&Alo[r][c4] = tl;
        }
#pragma unroll
        for (int it = 0; it < 2; it++) {
            int slot = tid + it*256;
            int col = slot & 63, kk0 = (slot >> 6) * 4;
            __nv_bfloat16 h0,l0,h1,l1,h2,l2,h3,l3;
            float v0 = W[(size_t)(kc+kk0+0)*Cc + col0 + col];
            float v1 = W[(size_t)(kc+kk0+1)*Cc + col0 + col];
            float v2 = W[(size_t)(kc+kk0+2)*Cc + col0 + col];
            float v3 = W[(size_t)(kc+kk0+3)*Cc + col0 + col];
            split2(v0, h0, l0); split2(v1, h1, l1);
            split2(v2, h2, l2); split2(v3, h3, l3);
            uint2 th; th.x = pk2(h0,h1); th.y = pk2(h2,h3);
            uint2 tl; tl.x = pk2(l0,l1); tl.y = pk2(l2,l3);
            *(uint2*)&Bshi[col][kk0] = th;
            *(uint2*)&Bslo[col][kk0] = tl;
        }
        __syncthreads();
#pragma unroll
        for (int ks = 0; ks < 2; ks++) {
            int kb = ks*16 + qc2;
            uint32_t a_hi[2][4], a_lo[2][4];
#pragma unroll
            for (int m = 0; m < 2; m++) {
                int r = wr + m*16 + qr;
                a_hi[m][0] = *(const uint32_t*)&Ahi[r][kb];
                a_hi[m][1] = *(const uint32_t*)&Ahi[r+8][kb];
                a_hi[m][2] = *(const uint32_t*)&Ahi[r][kb+8];
                a_hi[m][3] = *(const uint32_t*)&Ahi[r+8][kb+8];
                a_lo[m][0] = *(const uint32_t*)&Alo[r][kb];
                a_lo[m][1] = *(const uint32_t*)&Alo[r+8][kb];
                a_lo[m][2] = *(const uint32_t*)&Alo[r][kb+8];
                a_lo[m][3] = *(const uint32_t*)&Alo[r+8][kb+8];
            }
#pragma unroll
            for (int nf = 0; nf < 4; nf++) {
                int cn = wc + nf*8 + qr;
                uint32_t b_hi[2], b_lo[2];
                b_hi[0] = *(const uint32_t*)&Bshi[cn][kb];
                b_hi[1] = *(const uint32_t*)&Bshi[cn][kb+8];
                b_lo[0] = *(const uint32_t*)&Bslo[cn][kb];
                b_lo[1] = *(const uint32_t*)&Bslo[cn][kb+8];
#pragma unroll
                for (int m = 0; m < 2; m++) {
                    mma_bf16(acc[m][nf], a_hi[m], b_hi);
                    mma_bf16(acc[m][nf], a_hi[m], b_lo);
                    mma_bf16(acc[m][nf], a_lo[m], b_hi);
                }
            }
        }
        __syncthreads();
    }

    int h = blockIdx.y;
#pragma unroll
    for (int m = 0; m < 2; m++) {
#pragma unroll
        for (int e = 0; e < 2; e++) {
            int rg = row0 + wr + m*16 + qr + e*8;
            int bb = rg >> 11, sq = rg & 2047;
            float rsc;
            if (z == 0)      rsc = 0.125f;
            else if (z == 1) rsc = kw[bb*Mm + sq] * LOG2E;
            else             rsc = 1.0f;
#pragma unroll
            for (int nf = 0; nf < 4; nf++) {
                int d = wc + nf*8 + qc2;
                float v0 = (acc[m][nf][e*2+0] + bias[col0+d])   * rsc;
                float v1 = (acc[m][nf][e*2+1] + bias[col0+d+1]) * rsc;
                __nv_bfloat16 h0, l0, h1, l1;
                split2(v0, h0, l0); split2(v1, h1, l1);
                if (z != 2) {
                    size_t o = ((size_t)((bb*Hh + h)*2048 + sq))*64 + d;
                    __nv_bfloat162 th; th.x = h0; th.y = h1;
                    __nv_bfloat162 tl; tl.x = l0; tl.y = l1;
                    *(__nv_bfloat162*)&Ohi[o] = th;
                    *(__nv_bfloat162*)&Olo[o] = tl;
                } else {
                    size_t o = ((size_t)((bb*Hh + h)*64 + d))*2048 + sq;
                    Ohi[o] = h0; Ohi[o + 2048] = h1;
                    Olo[o] = l0; Olo[o + 2048] = l1;
                }
            }
        }
    }
}

// ---------------- K2: scores+exp+rowsum.  m split 4 ways for occupancy ----------
// grid: (m-split 4, n-blocks 32, b 4) = 512 CTAs, block 256 (4 row-groups x 2 m-halves)
__global__ __launch_bounds__(256) void scores_kernel(
    const int* __restrict__ kmask, const float* __restrict__ af,
    const int* __restrict__ amask, float* __restrict__ out_attn)
{
    __shared__ float Fa[64][68];                  // af (0 if masked); 64-col tile
    __shared__ float Fb[64][68];                  // 0 (-127 if masked)
    __shared__ __nv_bfloat16 Kh[64][72], Kl[64][72];
    __shared__ float s_rs[2][64];

    int tid = threadIdx.x, lane = tid & 31, warp = tid >> 5;
    int qr = lane >> 2, qc2 = (lane & 3) * 2;
    int ms = blockIdx.x;
    int b = blockIdx.z;
    int n0 = blockIdx.y * 64;
    int wr = (warp & 3) * 16;       // warp row group (local)
    int wm = (warp >> 2) * 32;      // warp m-half within 64-chunk
    int n_lo = n0 + wr + qr;
    int mbase = ms * 512;

    float rs[8][2];
#pragma unroll
    for (int h = 0; h < 8; h++) { rs[h][0] = 0.0f; rs[h][1] = 0.0f; }

    for (int mb = mbase; mb < mbase + 512; mb += 64) {
        __syncthreads();
        // build Fa/Fb tiles: 64 rows x 64 cols (af/amask read once; kmask L1-hot)
#pragma unroll
        for (int i = tid; i < 64*16; i += 256) {
            int r = i >> 4, c4 = (i & 15) * 4;
            size_t gi = ((size_t)(b*Nn + n0 + r))*Mm + mb + c4;
            float4 a  = *(const float4*)&af[gi];
            int4   am = *(const int4*)&amask[gi];
            int4   km = *(const int4*)&kmask[b*Mm + mb + c4];
            float4 fa, fb;
            fa.x = (am.x | km.x) ? 0.0f : a.x;  fb.x = (am.x | km.x) ? -127.0f : 0.0f;
            fa.y = (am.y | km.y) ? 0.0f : a.y;  fb.y = (am.y | km.y) ? -127.0f : 0.0f;
            fa.z = (am.z | km.z) ? 0.0f : a.z;  fb.z = (am.z | km.z) ? -127.0f : 0.0f;
            fa.w = (am.w | km.w) ? 0.0f : a.w;  fb.w = (am.w | km.w) ? -127.0f : 0.0f;
            *(float4*)&Fa[r][c4] = fa;
            *(float4*)&Fb[r][c4] = fb;
        }
        __syncthreads();

#pragma unroll 1
        for (int h = 0; h < 8; h++) {
            int bh = b*Hh + h;
            uint32_t q_hi[4][4], q_lo[4][4];
            {
                const __nv_bfloat16* qh = g_qhi + ((size_t)bh*Nn + n_lo)*64;
                const __nv_bfloat16* ql = g_qlo + ((size_t)bh*Nn + n_lo)*64;
#pragma unroll
                for (int ks = 0; ks < 4; ks++) {
                    int kb = ks*16 + qc2;
                    q_hi[ks][0] = *(const uint32_t*)&qh[kb];
                    q_hi[ks][1] = *(const uint32_t*)&qh[8*64 + kb];
                    q_hi[ks][2] = *(const uint32_t*)&qh[kb + 8];
                    q_hi[ks][3] = *(const uint32_t*)&qh[8*64 + kb + 8];
                    q_lo[ks][0] = *(const uint32_t*)&ql[kb];
                    q_lo[ks][1] = *(const uint32_t*)&ql[8*64 + kb];
                    q_lo[ks][2] = *(const uint32_t*)&ql[kb + 8];
                    q_lo[ks][3] = *(const uint32_t*)&ql[8*64 + kb + 8];
                }
            }
            __syncthreads();
            {   // stage K chunk (64 m x 64 dh, hi/lo)
                const __nv_bfloat16* kh = g_khi + ((size_t)bh*Mm + mb)*64;
                const __nv_bfloat16* kl = g_klo + ((size_t)bh*Mm + mb)*64;
#pragma unroll
                for (int i = tid; i < 64*16; i += 256) {
                    int r = i >> 4, c4 = (i & 15) * 4;
                    *(uint2*)&Kh[r][c4] = *(const uint2*)&kh[(size_t)r*64 + c4];
                    *(uint2*)&Kl[r][c4] = *(const uint2*)&kl[(size_t)r*64 + c4];
                }
            }
            __syncthreads();

            float sc[4][4];
#pragma unroll
            for (int nf = 0; nf < 4; nf++)
#pragma unroll
                for (int e = 0; e < 4; e++) sc[nf][e] = 0.0f;
#pragma unroll
            for (int ks = 0; ks < 4; ks++) {
                int kb = ks*16 + qc2;
#pragma unroll
                for (int nf = 0; nf < 4; nf++) {
                    int mcol = wm + nf*8 + qr;
                    uint32_t bhh[2], bll[2];
                    bhh[0] = *(const uint32_t*)&Kh[mcol][kb];
                    bhh[1] = *(const uint32_t*)&Kh[mcol][kb+8];
                    bll[0] = *(const uint32_t*)&Kl[mcol][kb];
                    bll[1] = *(const uint32_t*)&Kl[mcol][kb+8];
                    mma_bf16(sc[nf], q_hi[ks], bhh);
                    mma_bf16(sc[nf], q_hi[ks], bll);
                    mma_bf16(sc[nf], q_lo[ks], bhh);
                }
            }

            // epilogue: hybrid exp (nf<3 MUFU, nf==3 FMA-pipe poly)
            size_t at_lo = ((size_t)bh*Nn + n_lo)*Mm + mb + wm;
            size_t at_hi = at_lo + (size_t)8*Mm;
#pragma unroll
            for (int nf = 0; nf < 4; nf++) {
                int ml = nf*8 + qc2;
                int fc = wm + ml;
                float p0, p1, p2, p3;
                if (nf < 3) {
                    float2 fa0 = *(const float2*)&Fa[wr+qr][fc];
                    float2 fb0 = *(const float2*)&Fb[wr+qr][fc];
                    float2 fa1 = *(const float2*)&Fa[wr+qr+8][fc];
                    float2 fb1 = *(const float2*)&Fb[wr+qr+8][fc];
                    p0 = ex2f(fmaf(sc[nf][0], fa0.x, fb0.x));
                    p1 = ex2f(fmaf(sc[nf][1], fa0.y, fb0.y));
                    p2 = ex2f(fmaf(sc[nf][2], fa1.x, fb1.x));
                    p3 = ex2f(fmaf(sc[nf][3], fa1.y, fb1.y));
                } else {
                    uint64_t fa0 = *(const uint64_t*)&Fa[wr+qr][fc];
                    uint64_t fb0 = *(const uint64_t*)&Fb[wr+qr][fc];
                    uint64_t fa1 = *(const uint64_t*)&Fa[wr+qr+8][fc];
                    uint64_t fb1 = *(const uint64_t*)&Fb[wr+qr+8][fc];
                    exp2_pair(sc[nf][0], sc[nf][1], fa0, fb0, p0, p1);
                    exp2_pair(sc[nf][2], sc[nf][3], fa1, fb1, p2, p3);
                }
                rs[h][0] += p0 + p1;
                rs[h][1] += p2 + p3;
                *(float2*)&out_attn[at_lo + ml] = make_float2(p0, p1);
                *(float2*)&out_attn[at_hi + ml] = make_float2(p2, p3);
            }
        }
    }

    // finalize: per-head partial rowsums for this m-quarter
#pragma unroll
    for (int h = 0; h < 8; h++) {
        float r0 = rs[h][0], r1 = rs[h][1];
        r0 += __shfl_xor_sync(0xffffffffu, r0, 1);
        r0 += __shfl_xor_sync(0xffffffffu, r0, 2);
        r1 += __shfl_xor_sync(0xffffffffu, r1, 1);
        r1 += __shfl_xor_sync(0xffffffffu, r1, 2);
        __syncthreads();
        if ((lane & 3) == 0) {
            s_rs[wm >> 5][wr + qr]     = r0;
            s_rs[wm >> 5][wr + qr + 8] = r1;
        }
        __syncthreads();
        if (tid < 64)
            g_rs4[ms][(size_t)(b*Hh + h)*Nn + n0 + tid] = s_rs[0][tid] + s_rs[1][tid];
    }
}

// ---------------- K3: normalize attn in place + AV (hi/lo p, 3 MMAs) ------
// grid: (n-blocks 16, bh 32)  block 256
__global__ __launch_bounds__(256) void av_kernel(
    float* __restrict__ out_hidden, float* __restrict__ out_attn)
{
    __shared__ __nv_bfloat16 Vth[64][72], Vtl[64][72];  // [dh][m-chunk]

    int tid = threadIdx.x, lane = tid & 31, warp = tid >> 5;
    int qr = lane >> 2, qc2 = (lane & 3) * 2;
    int bh = blockIdx.y, b = bh >> 3, h = bh & 7;
    int n0 = blockIdx.x * 128;
    int wrow = warp * 16;
    int n_lo = n0 + wrow + qr;

    size_t ri = (size_t)bh*Nn + n_lo;
    float inv_lo = 1.0f / (g_rs4[0][ri] + g_rs4[1][ri] + g_rs4[2][ri] + g_rs4[3][ri]);
    float inv_hi = 1.0f / (g_rs4[0][ri+8] + g_rs4[1][ri+8] + g_rs4[2][ri+8] + g_rs4[3][ri+8]);

    float hid[8][4];
#pragma unroll
    for (int nf = 0; nf < 8; nf++)
#pragma unroll
        for (int e = 0; e < 4; e++) hid[nf][e] = 0.0f;

    size_t at_lo = ((size_t)bh*Nn + n_lo)*Mm;
    size_t at_hi = at_lo + (size_t)8*Mm;
    const __nv_bfloat16* vh = g_vhi + (size_t)bh*64*Mm;
    const __nv_bfloat16* vl = g_vlo + (size_t)bh*64*Mm;

    for (int m0 = 0; m0 < Mm; m0 += 64) {
        __syncthreads();
#pragma unroll
        for (int i = tid; i < 64*16; i += 256) {
            int d = i >> 4, c4 = (i & 15) * 4;
            *(uint2*)&Vth[d][c4] = *(const uint2*)&vh[(size_t)d*Mm + m0 + c4];
            *(uint2*)&Vtl[d][c4] = *(const uint2*)&vl[(size_t)d*Mm + m0 + c4];
        }
        __syncthreads();

        // read p, normalize, write back, build hi/lo A fragments
        uint32_t pa_hi[4][4], pa_lo[4][4];
#pragma unroll
        for (int kf = 0; kf < 4; kf++) {
            int ml = m0 + kf*16;
            float2 v0 = *(float2*)&out_attn[at_lo + ml + qc2];
            float2 v1 = *(float2*)&out_attn[at_hi + ml + qc2];
            float2 v2 = *(float2*)&out_attn[at_lo + ml + 8 + qc2];
            float2 v3 = *(float2*)&out_attn[at_hi + ml + 8 + qc2];
            v0.x *= inv_lo; v0.y *= inv_lo; v2.x *= inv_lo; v2.y *= inv_lo;
            v1.x *= inv_hi; v1.y *= inv_hi; v3.x *= inv_hi; v3.y *= inv_hi;
            *(float2*)&out_attn[at_lo + ml + qc2]     = v0;
            *(float2*)&out_attn[at_hi + ml + qc2]     = v1;
            *(float2*)&out_attn[at_lo + ml + 8 + qc2] = v2;
            *(float2*)&out_attn[at_hi + ml + 8 + qc2] = v3;
            __nv_bfloat16 h0,l0,h1,l1;
            split2(v0.x, h0, l0); split2(v0.y, h1, l1);
            pa_hi[kf][0] = pk2(h0, h1); pa_lo[kf][0] = pk2(l0, l1);
            split2(v1.x, h0, l0); split2(v1.y, h1, l1);
            pa_hi[kf][1] = pk2(h0, h1); pa_lo[kf][1] = pk2(l0, l1);
            split2(v2.x, h0, l0); split2(v2.y, h1, l1);
            pa_hi[kf][2] = pk2(h0, h1); pa_lo[kf][2] = pk2(l0, l1);
            split2(v3.x, h0, l0); split2(v3.y, h1, l1);
            pa_hi[kf][3] = pk2(h0, h1); pa_lo[kf][3] = pk2(l0, l1);
        }

        // hidden += p @ V (3-way split), V from transposed smem
#pragma unroll
        for (int ks = 0; ks < 4; ks++) {
            int mr = ks*16 + qc2;
#pragma unroll
            for (int nf = 0; nf < 8; nf++) {
                int dc = nf*8 + qr;
                uint32_t bhh[2], bll[2];
                bhh[0] = *(const uint32_t*)&Vth[dc][mr];
                bhh[1] = *(const uint32_t*)&Vth[dc][mr+8];
                bll[0] = *(const uint32_t*)&Vtl[dc][mr];
                bll[1] = *(const uint32_t*)&Vtl[dc][mr+8];
                mma_bf16(hid[nf], pa_hi[ks], bhh);
                mma_bf16(hid[nf], pa_hi[ks], bll);
                mma_bf16(hid[nf], pa_lo[ks], bhh);
            }
        }
    }

#pragma unroll
    for (int nf = 0; nf < 8; nf++) {
        int d = nf*8 + qc2;
        size_t o_lo = ((size_t)b*Nn + n_lo)*Cc + h*64 + d;
        size_t o_hi = o_lo + (size_t)8*Cc;
        *(float2*)&out_hidden[o_lo] = make_float2(hid[nf][0], hid[nf][1]);
        *(float2*)&out_hidden[o_hi] = make_float2(hid[nf][2], hid[nf][3]);
    }
}

// ---------------- launch ----------------
extern "C" void kernel_launch(void* const* d_in, const int* in_sizes, int n_in,
                              void* d_out, int out_size) {
    const float* xq    = (const float*)d_in[0];
    const float* xk    = (const float*)d_in[1];
    const float* xv    = (const float*)d_in[2];
    const float* kw    = (const float*)d_in[3];
    const int*   kmask = (const int*)d_in[4];
    const float* af    = (const float*)d_in[5];
    const int*   amask = (const int*)d_in[6];
    const float* Wq    = (const float*)d_in[7];
    const float* bq    = (const float*)d_in[8];
    const float* Wk    = (const float*)d_in[9];
    const float* bk    = (const float*)d_in[10];
    const float* Wv    = (const float*)d_in[11];
    const float* bv    = (const float*)d_in[12];

    float* out_hidden = (float*)d_out;
    float* out_attn   = out_hidden + (size_t)Bb*Nn*Cc;

    proj_kernel<<<dim3(64, 8, 3), 256>>>(xq, xk, xv, Wq, bq, Wk, bk, Wv, bv, kw);
    scores_kernel<<<dim3(4, 32, 4), 256>>>(kmask, af, amask, out_attn);
    av_kernel<<<dim3(16, 32), 256>>>(out_hidden, out_attn);
}

// round 9
// speedup vs baseline: 1.3498x; 1.3498x over previous
#include <cuda_runtime.h>
#include <cuda_bf16.h>
#include <stdint.h>

#define Bb 4
#define Nn 2048
#define Mm 2048
#define Cc 512
#define Hh 8
#define DHd 64
#define LOG2E 1.4426950408889634f

// ---------------- static scratch (no allocations allowed) ----------------
__device__ __nv_bfloat16 g_qhi[Bb*Hh*Nn*DHd];   // [bh][n][dh], pre-scaled by 1/8
__device__ __nv_bfloat16 g_qlo[Bb*Hh*Nn*DHd];
__device__ __nv_bfloat16 g_khi[Bb*Hh*Mm*DHd];   // [bh][m][dh], pre-scaled by kw*log2e
__device__ __nv_bfloat16 g_klo[Bb*Hh*Mm*DHd];
__device__ __nv_bfloat16 g_vhi[Bb*Hh*DHd*Mm];   // TRANSPOSED: [bh][dh][m]
__device__ __nv_bfloat16 g_vlo[Bb*Hh*DHd*Mm];
__device__ float        g_inv[Bb*Hh*Nn];        // 1/rowsum

// ---------------- helpers ----------------
__device__ __forceinline__ void mma_bf16(float c[4], const uint32_t a[4], const uint32_t b[2]) {
    asm volatile(
        "mma.sync.aligned.m16n8k16.row.col.f32.bf16.bf16.f32 "
        "{%0,%1,%2,%3}, {%4,%5,%6,%7}, {%8,%9}, {%0,%1,%2,%3};\n"
        : "+f"(c[0]), "+f"(c[1]), "+f"(c[2]), "+f"(c[3])
        : "r"(a[0]), "r"(a[1]), "r"(a[2]), "r"(a[3]), "r"(b[0]), "r"(b[1]));
}

__device__ __forceinline__ void split2(float x, __nv_bfloat16 &hi, __nv_bfloat16 &lo) {
    hi = __float2bfloat16_rn(x);
    lo = __float2bfloat16_rn(x - __bfloat162float(hi));
}

__device__ __forceinline__ uint32_t pk2(__nv_bfloat16 a, __nv_bfloat16 b) {
    return (uint32_t)__bfloat16_as_ushort(a) | ((uint32_t)__bfloat16_as_ushort(b) << 16);
}

// guaranteed MUFU.EX2
__device__ __forceinline__ float ex2f(float x) {
    float r;
    asm("ex2.approx.ftz.f32 %0, %1;" : "=f"(r) : "f"(x));
    return r;
}

// ---------------- K1: fused projections (X@W + b), bf16-split mma ----------------
// grid: (64, 8, 3)  block: 256
__global__ __launch_bounds__(256) void proj_kernel(
    const float* __restrict__ xq, const float* __restrict__ xk, const float* __restrict__ xv,
    const float* __restrict__ Wq, const float* __restrict__ bq,
    const float* __restrict__ Wk, const float* __restrict__ bk,
    const float* __restrict__ Wv, const float* __restrict__ bv,
    const float* __restrict__ kw)
{
    const float* X; const float* W; const float* bias;
    __nv_bfloat16 *Ohi, *Olo;
    int z = blockIdx.z;
    if (z == 0)      { X = xq; W = Wq; bias = bq; Ohi = g_qhi; Olo = g_qlo; }
    else if (z == 1) { X = xk; W = Wk; bias = bk; Ohi = g_khi; Olo = g_klo; }
    else             { X = xv; W = Wv; bias = bv; Ohi = g_vhi; Olo = g_vlo; }

    __shared__ __nv_bfloat16 Ahi[128][40], Alo[128][40];   // [row][k], k-chunk 32, pad 8
    __shared__ __nv_bfloat16 Bshi[64][40], Bslo[64][40];   // [col][k] transposed

    int tid = threadIdx.x, lane = tid & 31, warp = tid >> 5;
    int row0 = blockIdx.x * 128;
    int col0 = blockIdx.y * 64;
    int wr = (warp >> 1) * 32, wc = (warp & 1) * 32;
    int qr = lane >> 2, qc2 = (lane & 3) * 2;

    float acc[2][4][4];
#pragma unroll
    for (int m = 0; m < 2; m++)
#pragma unroll
        for (int n = 0; n < 4; n++)
#pragma unroll
            for (int e = 0; e < 4; e++) acc[m][n][e] = 0.0f;

    for (int kc = 0; kc < Cc; kc += 32) {
#pragma unroll
        for (int i = tid; i < 128*8; i += 256) {
            int r = i >> 3, c4 = (i & 7) * 4;
            float4 v = *(const float4*)&X[(size_t)(row0 + r)*Cc + kc + c4];
            __nv_bfloat16 h0,l0,h1,l1,h2,l2,h3,l3;
            split2(v.x, h0, l0); split2(v.y, h1, l1);
            split2(v.z, h2, l2); split2(v.w, h3, l3);
            uint2 th; th.x = pk2(h0,h1); th.y = pk2(h2,h3);
            uint2 tl; tl.x = pk2(l0,l1); tl.y = pk2(l2,l3);
            *(uint2*)&Ahi[r][c4] = th;
            *(uint2*)&Alo[r][c4] = tl;
        }
#pragma unroll
        for (int it = 0; it < 2; it++) {
            int slot = tid + it*256;
            int col = slot & 63, kk0 = (slot >> 6) * 4;
            __nv_bfloat16 h0,l0,h1,l1,h2,l2,h3,l3;
            float v0 = W[(size_t)(kc+kk0+0)*Cc + col0 + col];
            float v1 = W[(size_t)(kc+kk0+1)*Cc + col0 + col];
            float v2 = W[(size_t)(kc+kk0+2)*Cc + col0 + col];
            float v3 = W[(size_t)(kc+kk0+3)*Cc + col0 + col];
            split2(v0, h0, l0); split2(v1, h1, l1);
            split2(v2, h2, l2); split2(v3, h3, l3);
            uint2 th; th.x = pk2(h0,h1); th.y = pk2(h2,h3);
            uint2 tl; tl.x = pk2(l0,l1); tl.y = pk2(l2,l3);
            *(uint2*)&Bshi[col][kk0] = th;
            *(uint2*)&Bslo[col][kk0] = tl;
        }
        __syncthreads();
#pragma unroll
        for (int ks = 0; ks < 2; ks++) {
            int kb = ks*16 + qc2;
            uint32_t a_hi[2][4], a_lo[2][4];
#pragma unroll
            for (int m = 0; m < 2; m++) {
                int r = wr + m*16 + qr;
                a_hi[m][0] = *(const uint32_t*)&Ahi[r][kb];
                a_hi[m][1] = *(const uint32_t*)&Ahi[r+8][kb];
                a_hi[m][2] = *(const uint32_t*)&Ahi[r][kb+8];
                a_hi[m][3] = *(const uint32_t*)&Ahi[r+8][kb+8];
                a_lo[m][0] = *(const uint32_t*)&Alo[r][kb];
                a_lo[m][1] = *(const uint32_t*)&Alo[r+8][kb];
                a_lo[m][2] = *(const uint32_t*)&Alo[r][kb+8];
                a_lo[m][3] = *(const uint32_t*)&Alo[r+8][kb+8];
            }
#pragma unroll
            for (int nf = 0; nf < 4; nf++) {
                int cn = wc + nf*8 + qr;
                uint32_t b_hi[2], b_lo[2];
                b_hi[0] = *(const uint32_t*)&Bshi[cn][kb];
                b_hi[1] = *(const uint32_t*)&Bshi[cn][kb+8];
                b_lo[0] = *(const uint32_t*)&Bslo[cn][kb];
                b_lo[1] = *(const uint32_t*)&Bslo[cn][kb+8];
#pragma unroll
                for (int m = 0; m < 2; m++) {
                    mma_bf16(acc[m][nf], a_hi[m], b_hi);
                    mma_bf16(acc[m][nf], a_hi[m], b_lo);
                    mma_bf16(acc[m][nf], a_lo[m], b_hi);
                }
            }
        }
        __syncthreads();
    }

    int h = blockIdx.y;
#pragma unroll
    for (int m = 0; m < 2; m++) {
#pragma unroll
        for (int e = 0; e < 2; e++) {
            int rg = row0 + wr + m*16 + qr + e*8;
            int bb = rg >> 11, sq = rg & 2047;
            float rsc;
            if (z == 0)      rsc = 0.125f;
            else if (z == 1) rsc = kw[bb*Mm + sq] * LOG2E;
            else             rsc = 1.0f;
#pragma unroll
            for (int nf = 0; nf < 4; nf++) {
                int d = wc + nf*8 + qc2;
                float v0 = (acc[m][nf][e*2+0] + bias[col0+d])   * rsc;
                float v1 = (acc[m][nf][e*2+1] + bias[col0+d+1]) * rsc;
                __nv_bfloat16 h0, l0, h1, l1;
                split2(v0, h0, l0); split2(v1, h1, l1);
                if (z != 2) {
                    size_t o = ((size_t)((bb*Hh + h)*2048 + sq))*64 + d;
                    __nv_bfloat162 th; th.x = h0; th.y = h1;
                    __nv_bfloat162 tl; tl.x = l0; tl.y = l1;
                    *(__nv_bfloat162*)&Ohi[o] = th;
                    *(__nv_bfloat162*)&Olo[o] = tl;
                } else {
                    size_t o = ((size_t)((bb*Hh + h)*64 + d))*2048 + sq;
                    Ohi[o] = h0; Ohi[o + 2048] = h1;
                    Olo[o] = l0; Olo[o + 2048] = l1;
                }
            }
        }
    }
}

// ---------------- K2: fused attention (scores, exp, rowsum, AV, unnorm attn) ------
// grid: (h 8, n-blocks 16, b 4)  block 256 (8 warps x 16 rows = 128 q rows).
// Head is the FASTEST grid dim: the 8 CTAs of one (b, n-block) read identical
// af/amask slices concurrently -> 7/8 of that traffic hits L2 instead of DRAM.
__global__ __launch_bounds__(256) void attn_kernel(
    const int* __restrict__ kmask, const float* __restrict__ af,
    const int* __restrict__ amask,
    float* __restrict__ out_hidden, float* __restrict__ out_attn)
{
    __shared__ __nv_bfloat16 Kh[64][72], Kl[64][72];    // [m][dh]
    __shared__ __nv_bfloat16 Vth[64][72], Vtl[64][72];  // [dh][m]
    __shared__ int s_km[64];

    int tid = threadIdx.x, lane = tid & 31, warp = tid >> 5;
    int qr = lane >> 2, qc2 = (lane & 3) * 2;
    int h = blockIdx.x, b = blockIdx.z;
    int bh = b*Hh + h;
    int n0 = blockIdx.y * 128;
    int wrow = warp * 16;
    int n_lo = n0 + wrow + qr;

    // preload Q fragments (hi/lo) for this warp's 16 rows, all 64 dh
    uint32_t q_hi[4][4], q_lo[4][4];
    {
        const __nv_bfloat16* qh = g_qhi + ((size_t)bh*Nn + n_lo)*64;
        const __nv_bfloat16* ql = g_qlo + ((size_t)bh*Nn + n_lo)*64;
#pragma unroll
        for (int ks = 0; ks < 4; ks++) {
            int kb = ks*16 + qc2;
            q_hi[ks][0] = *(const uint32_t*)&qh[kb];
            q_hi[ks][1] = *(const uint32_t*)&qh[8*64 + kb];
            q_hi[ks][2] = *(const uint32_t*)&qh[kb + 8];
            q_hi[ks][3] = *(const uint32_t*)&qh[8*64 + kb + 8];
            q_lo[ks][0] = *(const uint32_t*)&ql[kb];
            q_lo[ks][1] = *(const uint32_t*)&ql[8*64 + kb];
            q_lo[ks][2] = *(const uint32_t*)&ql[kb + 8];
            q_lo[ks][3] = *(const uint32_t*)&ql[8*64 + kb + 8];
        }
    }

    float hid[8][4];
#pragma unroll
    for (int nf = 0; nf < 8; nf++)
#pragma unroll
        for (int e = 0; e < 4; e++) hid[nf][e] = 0.0f;
    float rs_lo = 0.0f, rs_hi = 0.0f;

    size_t af_lo_row = ((size_t)b*Nn + n_lo)*Mm;
    size_t af_hi_row = af_lo_row + (size_t)8*Mm;
    size_t at_lo_row = ((size_t)bh*Nn + n_lo)*Mm;
    size_t at_hi_row = at_lo_row + (size_t)8*Mm;

    const __nv_bfloat16* khp = g_khi + (size_t)bh*Mm*64;
    const __nv_bfloat16* klp = g_klo + (size_t)bh*Mm*64;
    const __nv_bfloat16* vhp = g_vhi + (size_t)bh*64*Mm;
    const __nv_bfloat16* vlp = g_vlo + (size_t)bh*64*Mm;

    for (int m0 = 0; m0 < Mm; m0 += 64) {
        __syncthreads();
        // stage K [m][dh] and V^T [dh][m] chunks (hi/lo)
#pragma unroll
        for (int i = tid; i < 64*16; i += 256) {
            int r = i >> 4, c4 = (i & 15) * 4;
            *(uint2*)&Kh[r][c4]  = *(const uint2*)&khp[(size_t)(m0 + r)*64 + c4];
            *(uint2*)&Kl[r][c4]  = *(const uint2*)&klp[(size_t)(m0 + r)*64 + c4];
            *(uint2*)&Vth[r][c4] = *(const uint2*)&vhp[(size_t)r*Mm + m0 + c4];
            *(uint2*)&Vtl[r][c4] = *(const uint2*)&vlp[(size_t)r*Mm + m0 + c4];
        }
        if (tid < 64) s_km[tid] = kmask[b*Mm + m0 + tid];
        __syncthreads();

        // QK^T: s (16 x 64) fp32, 3-way bf16 split
        float sc[8][4];
#pragma unroll
        for (int nf = 0; nf < 8; nf++)
#pragma unroll
            for (int e = 0; e < 4; e++) sc[nf][e] = 0.0f;
#pragma unroll
        for (int ks = 0; ks < 4; ks++) {
            int kb = ks*16 + qc2;
#pragma unroll
            for (int nf = 0; nf < 8; nf++) {
                int mc = nf*8 + qr;
                uint32_t bhh[2], bll[2];
                bhh[0] = *(const uint32_t*)&Kh[mc][kb];
                bhh[1] = *(const uint32_t*)&Kh[mc][kb+8];
                bll[0] = *(const uint32_t*)&Kl[mc][kb];
                bll[1] = *(const uint32_t*)&Kl[mc][kb+8];
                mma_bf16(sc[nf], q_hi[ks], bhh);
                mma_bf16(sc[nf], q_hi[ks], bll);
                mma_bf16(sc[nf], q_lo[ks], bhh);
            }
        }

        // epilogue: p = mask ? 0 : 2^(s*af)  (kw, 1/8, log2e folded into K/Q)
        uint32_t pa_hi[4][4], pa_lo[4][4];
#pragma unroll
        for (int nf = 0; nf < 8; nf++) {
            int ml = nf*8 + qc2;
            float2 afl = *(const float2*)&af[af_lo_row + m0 + ml];
            float2 afh = *(const float2*)&af[af_hi_row + m0 + ml];
            int2 aml = *(const int2*)&amask[af_lo_row + m0 + ml];
            int2 amh = *(const int2*)&amask[af_hi_row + m0 + ml];
            int km0 = s_km[ml], km1 = s_km[ml+1];
            float p0 = (km0 | aml.x) ? 0.0f : ex2f(sc[nf][0] * afl.x);
            float p1 = (km1 | aml.y) ? 0.0f : ex2f(sc[nf][1] * afl.y);
            float p2 = (km0 | amh.x) ? 0.0f : ex2f(sc[nf][2] * afh.x);
            float p3 = (km1 | amh.y) ? 0.0f : ex2f(sc[nf][3] * afh.y);
            rs_lo += p0 + p1;
            rs_hi += p2 + p3;
            *(float2*)&out_attn[at_lo_row + m0 + ml] = make_float2(p0, p1);
            *(float2*)&out_attn[at_hi_row + m0 + ml] = make_float2(p2, p3);
            __nv_bfloat16 h0,l0,h1,l1,h2,l2,h3,l3;
            split2(p0,h0,l0); split2(p1,h1,l1); split2(p2,h2,l2); split2(p3,h3,l3);
            int ks = nf >> 1, hf = (nf & 1) * 2;
            pa_hi[ks][hf+0] = pk2(h0, h1);
            pa_hi[ks][hf+1] = pk2(h2, h3);
            pa_lo[ks][hf+0] = pk2(l0, l1);
            pa_lo[ks][hf+1] = pk2(l2, l3);
        }

        // AV: hidden += p @ V (3-way split), V from transposed smem
#pragma unroll
        for (int ks = 0; ks < 4; ks++) {
            int mr = ks*16 + qc2;
#pragma unroll
            for (int nf = 0; nf < 8; nf++) {
                int dc = nf*8 + qr;
                uint32_t bhh[2], bll[2];
                bhh[0] = *(const uint32_t*)&Vth[dc][mr];
                bhh[1] = *(const uint32_t*)&Vth[dc][mr+8];
                bll[0] = *(const uint32_t*)&Vtl[dc][mr];
                bll[1] = *(const uint32_t*)&Vtl[dc][mr+8];
                mma_bf16(hid[nf], pa_hi[ks], bhh);
                mma_bf16(hid[nf], pa_hi[ks], bll);
                mma_bf16(hid[nf], pa_lo[ks], bhh);
            }
        }
    }

    // rowsum reduce across the quad, write inverse, write normalized hidden
    rs_lo += __shfl_xor_sync(0xffffffffu, rs_lo, 1);
    rs_lo += __shfl_xor_sync(0xffffffffu, rs_lo, 2);
    rs_hi += __shfl_xor_sync(0xffffffffu, rs_hi, 1);
    rs_hi += __shfl_xor_sync(0xffffffffu, rs_hi, 2);
    float inv_lo = 1.0f / rs_lo;
    float inv_hi = 1.0f / rs_hi;
    if ((lane & 3) == 0) {
        g_inv[(size_t)bh*Nn + n_lo]     = inv_lo;
        g_inv[(size_t)bh*Nn + n_lo + 8] = inv_hi;
    }
#pragma unroll
    for (int nf = 0; nf < 8; nf++) {
        int d = nf*8 + qc2;
        size_t o_lo = ((size_t)b*Nn + n_lo)*Cc + h*64 + d;
        size_t o_hi = o_lo + (size_t)8*Cc;
        *(float2*)&out_hidden[o_lo] = make_float2(hid[nf][0]*inv_lo, hid[nf][1]*inv_lo);
        *(float2*)&out_hidden[o_hi] = make_float2(hid[nf][2]*inv_hi, hid[nf][3]*inv_hi);
    }
}

// ---------------- K3: normalize attn in place ----------------
__global__ __launch_bounds__(256) void norm_kernel(float4* __restrict__ attn4) {
    int i = blockIdx.x * 256 + threadIdx.x;     // 33,554,432 float4s total
    float4 v = attn4[i];
    float inv = g_inv[i >> 9];                  // 512 float4 per (b,h,n) row
    v.x *= inv; v.y *= inv; v.z *= inv; v.w *= inv;
    attn4[i] = v;
}

// ---------------- launch ----------------
extern "C" void kernel_launch(void* const* d_in, const int* in_sizes, int n_in,
                              void* d_out, int out_size) {
    const float* xq    = (const float*)d_in[0];
    const float* xk    = (const float*)d_in[1];
    const float* xv    = (const float*)d_in[2];
    const float* kw    = (const float*)d_in[3];
    const int*   kmask = (const int*)d_in[4];
    const float* af    = (const float*)d_in[5];
    const int*   amask = (const int*)d_in[6];
    const float* Wq    = (const float*)d_in[7];
    const float* bq    = (const float*)d_in[8];
    const float* Wk    = (const float*)d_in[9];
    const float* bk    = (const float*)d_in[10];
    const float* Wv    = (const float*)d_in[11];
    const float* bv    = (const float*)d_in[12];

    float* out_hidden = (float*)d_out;
    float* out_attn   = out_hidden + (size_t)Bb*Nn*Cc;

    proj_kernel<<<dim3(64, 8, 3), 256>>>(xq, xk, xv, Wq, bq, Wk, bk, Wv, bv, kw);
    attn_kernel<<<dim3(8, 16, 4), 256>>>(kmask, af, amask, out_hidden, out_attn);
    norm_kernel<<<131072, 256>>>((float4*)out_attn);
}

// round 10
// speedup vs baseline: 1.6660x; 1.2342x over previous
#include <cuda_runtime.h>
#include <cuda_bf16.h>
#include <stdint.h>

#define Bb 4
#define Nn 2048
#define Mm 2048
#define Cc 512
#define Hh 8
#define DHd 64
#define LOG2E 1.4426950408889634f

// ---------------- static scratch (no allocations allowed) ----------------
__device__ __nv_bfloat16 g_qhi[Bb*Hh*Nn*DHd];   // [bh][n][dh], pre-scaled by 1/8
__device__ __nv_bfloat16 g_qlo[Bb*Hh*Nn*DHd];
__device__ __nv_bfloat16 g_khi[Bb*Hh*Mm*DHd];   // [bh][m][dh], pre-scaled by kw*log2e
__device__ __nv_bfloat16 g_klo[Bb*Hh*Mm*DHd];
__device__ __nv_bfloat16 g_vhi[Bb*Hh*DHd*Mm];   // TRANSPOSED: [bh][dh][m]
__device__ __nv_bfloat16 g_vlo[Bb*Hh*DHd*Mm];
__device__ float        g_inv[Bb*Hh*Nn];        // 1/rowsum

// ---------------- helpers ----------------
__device__ __forceinline__ void mma_bf16(float c[4], const uint32_t a[4], const uint32_t b[2]) {
    asm volatile(
        "mma.sync.aligned.m16n8k16.row.col.f32.bf16.bf16.f32 "
        "{%0,%1,%2,%3}, {%4,%5,%6,%7}, {%8,%9}, {%0,%1,%2,%3};\n"
        : "+f"(c[0]), "+f"(c[1]), "+f"(c[2]), "+f"(c[3])
        : "r"(a[0]), "r"(a[1]), "r"(a[2]), "r"(a[3]), "r"(b[0]), "r"(b[1]));
}

__device__ __forceinline__ void split2(float x, __nv_bfloat16 &hi, __nv_bfloat16 &lo) {
    hi = __float2bfloat16_rn(x);
    lo = __float2bfloat16_rn(x - __bfloat162float(hi));
}

__device__ __forceinline__ uint32_t pk2(__nv_bfloat16 a, __nv_bfloat16 b) {
    return (uint32_t)__bfloat16_as_ushort(a) | ((uint32_t)__bfloat16_as_ushort(b) << 16);
}

// guaranteed MUFU.EX2
__device__ __forceinline__ float ex2f(float x) {
    float r;
    asm("ex2.approx.ftz.f32 %0, %1;" : "=f"(r) : "f"(x));
    return r;
}

// 16B async copy gmem -> smem (LDGSTS)
__device__ __forceinline__ void cpa16(void* smem, const void* gmem) {
    uint32_t s = (uint32_t)__cvta_generic_to_shared(smem);
    asm volatile("cp.async.cg.shared.global [%0], [%1], 16;" :: "r"(s), "l"(gmem));
}

// ---------------- K1: fused projections (X@W + b), bf16-split mma ----------------
// grid: (64, 8, 3)  block: 256
__global__ __launch_bounds__(256) void proj_kernel(
    const float* __restrict__ xq, const float* __restrict__ xk, const float* __restrict__ xv,
    const float* __restrict__ Wq, const float* __restrict__ bq,
    const float* __restrict__ Wk, const float* __restrict__ bk,
    const float* __restrict__ Wv, const float* __restrict__ bv,
    const float* __restrict__ kw)
{
    const float* X; const float* W; const float* bias;
    __nv_bfloat16 *Ohi, *Olo;
    int z = blockIdx.z;
    if (z == 0)      { X = xq; W = Wq; bias = bq; Ohi = g_qhi; Olo = g_qlo; }
    else if (z == 1) { X = xk; W = Wk; bias = bk; Ohi = g_khi; Olo = g_klo; }
    else             { X = xv; W = Wv; bias = bv; Ohi = g_vhi; Olo = g_vlo; }

    __shared__ __nv_bfloat16 Ahi[128][40], Alo[128][40];   // [row][k], k-chunk 32, pad 8
    __shared__ __nv_bfloat16 Bshi[64][40], Bslo[64][40];   // [col][k] transposed

    int tid = threadIdx.x, lane = tid & 31, warp = tid >> 5;
    int row0 = blockIdx.x * 128;
    int col0 = blockIdx.y * 64;
    int wr = (warp >> 1) * 32, wc = (warp & 1) * 32;
    int qr = lane >> 2, qc2 = (lane & 3) * 2;

    float acc[2][4][4];
#pragma unroll
    for (int m = 0; m < 2; m++)
#pragma unroll
        for (int n = 0; n < 4; n++)
#pragma unroll
            for (int e = 0; e < 4; e++) acc[m][n][e] = 0.0f;

    for (int kc = 0; kc < Cc; kc += 32) {
#pragma unroll
        for (int i = tid; i < 128*8; i += 256) {
            int r = i >> 3, c4 = (i & 7) * 4;
            float4 v = *(const float4*)&X[(size_t)(row0 + r)*Cc + kc + c4];
            __nv_bfloat16 h0,l0,h1,l1,h2,l2,h3,l3;
            split2(v.x, h0, l0); split2(v.y, h1, l1);
            split2(v.z, h2, l2); split2(v.w, h3, l3);
            uint2 th; th.x = pk2(h0,h1); th.y = pk2(h2,h3);
            uint2 tl; tl.x = pk2(l0,l1); tl.y = pk2(l2,l3);
            *(uint2*)&Ahi[r][c4] = th;
            *(uint2*)&Alo[r][c4] = tl;
        }
#pragma unroll
        for (int it = 0; it < 2; it++) {
            int slot = tid + it*256;
            int col = slot & 63, kk0 = (slot >> 6) * 4;
            __nv_bfloat16 h0,l0,h1,l1,h2,l2,h3,l3;
            float v0 = W[(size_t)(kc+kk0+0)*Cc + col0 + col];
            float v1 = W[(size_t)(kc+kk0+1)*Cc + col0 + col];
            float v2 = W[(size_t)(kc+kk0+2)*Cc + col0 + col];
            float v3 = W[(size_t)(kc+kk0+3)*Cc + col0 + col];
            split2(v0, h0, l0); split2(v1, h1, l1);
            split2(v2, h2, l2); split2(v3, h3, l3);
            uint2 th; th.x = pk2(h0,h1); th.y = pk2(h2,h3);
            uint2 tl; tl.x = pk2(l0,l1); tl.y = pk2(l2,l3);
            *(uint2*)&Bshi[col][kk0] = th;
            *(uint2*)&Bslo[col][kk0] = tl;
        }
        __syncthreads();
#pragma unroll
        for (int ks = 0; ks < 2; ks++) {
            int kb = ks*16 + qc2;
            uint32_t a_hi[2][4], a_lo[2][4];
#pragma unroll
            for (int m = 0; m < 2; m++) {
                int r = wr + m*16 + qr;
                a_hi[m][0] = *(const uint32_t*)&Ahi[r][kb];
                a_hi[m][1] = *(const uint32_t*)&Ahi[r+8][kb];
                a_hi[m][2] = *(const uint32_t*)&Ahi[r][kb+8];
                a_hi[m][3] = *(const uint32_t*)&Ahi[r+8][kb+8];
                a_lo[m][0] = *(const uint32_t*)&Alo[r][kb];
                a_lo[m][1] = *(const uint32_t*)&Alo[r+8][kb];
                a_lo[m][2] = *(const uint32_t*)&Alo[r][kb+8];
                a_lo[m][3] = *(const uint32_t*)&Alo[r+8][kb+8];
            }
#pragma unroll
            for (int nf = 0; nf < 4; nf++) {
                int cn = wc + nf*8 + qr;
                uint32_t b_hi[2], b_lo[2];
                b_hi[0] = *(const uint32_t*)&Bshi[cn][kb];
                b_hi[1] = *(const uint32_t*)&Bshi[cn][kb+8];
                b_lo[0] = *(const uint32_t*)&Bslo[cn][kb];
                b_lo[1] = *(const uint32_t*)&Bslo[cn][kb+8];
#pragma unroll
                for (int m = 0; m < 2; m++) {
                    mma_bf16(acc[m][nf], a_hi[m], b_hi);
                    mma_bf16(acc[m][nf], a_hi[m], b_lo);
                    mma_bf16(acc[m][nf], a_lo[m], b_hi);
                }
            }
        }
        __syncthreads();
    }

    int h = blockIdx.y;
#pragma unroll
    for (int m = 0; m < 2; m++) {
#pragma unroll
        for (int e = 0; e < 2; e++) {
            int rg = row0 + wr + m*16 + qr + e*8;
            int bb = rg >> 11, sq = rg & 2047;
            float rsc;
            if (z == 0)      rsc = 0.125f;
            else if (z == 1) rsc = kw[bb*Mm + sq] * LOG2E;
            else             rsc = 1.0f;
#pragma unroll
            for (int nf = 0; nf < 4; nf++) {
                int d = wc + nf*8 + qc2;
                float v0 = (acc[m][nf][e*2+0] + bias[col0+d])   * rsc;
                float v1 = (acc[m][nf][e*2+1] + bias[col0+d+1]) * rsc;
                __nv_bfloat16 h0, l0, h1, l1;
                split2(v0, h0, l0); split2(v1, h1, l1);
                if (z != 2) {
                    size_t o = ((size_t)((bb*Hh + h)*2048 + sq))*64 + d;
                    __nv_bfloat162 th; th.x = h0; th.y = h1;
                    __nv_bfloat162 tl; tl.x = l0; tl.y = l1;
                    *(__nv_bfloat162*)&Ohi[o] = th;
                    *(__nv_bfloat162*)&Olo[o] = tl;
                } else {
                    size_t o = ((size_t)((bb*Hh + h)*64 + d))*2048 + sq;
                    Ohi[o] = h0; Ohi[o + 2048] = h1;
                    Olo[o] = l0; Olo[o + 2048] = l1;
                }
            }
        }
    }
}

// ---------------- K2: fused attention with cp.async double-buffered K/V ------
// grid: (h 8, n-blocks 16, b 4)  block 256 (8 warps x 16 rows = 128 q rows).
// Head fastest in grid -> af/amask L2-shared across the 8 CTAs of a (b,nblk).
// Dynamic smem: Kh/Kl/Vth/Vtl [2][64][72] bf16 + s_km [2][64] int = 74,240 B.
#define TILE_B (64*72*2)        // one [64][72] bf16 buffer = 9216 B
__global__ __launch_bounds__(256) void attn_kernel(
    const int* __restrict__ kmask, const float* __restrict__ af,
    const int* __restrict__ amask,
    float* __restrict__ out_hidden, float* __restrict__ out_attn)
{
    extern __shared__ char dsm[];
    __nv_bfloat16 (*Kh)[64][72]  = (__nv_bfloat16(*)[64][72])(dsm);
    __nv_bfloat16 (*Kl)[64][72]  = (__nv_bfloat16(*)[64][72])(dsm + 2*TILE_B);
    __nv_bfloat16 (*Vth)[64][72] = (__nv_bfloat16(*)[64][72])(dsm + 4*TILE_B);
    __nv_bfloat16 (*Vtl)[64][72] = (__nv_bfloat16(*)[64][72])(dsm + 6*TILE_B);
    int* s_km = (int*)(dsm + 8*TILE_B);      // [2][64]

    int tid = threadIdx.x, lane = tid & 31, warp = tid >> 5;
    int qr = lane >> 2, qc2 = (lane & 3) * 2;
    int h = blockIdx.x, b = blockIdx.z;
    int bh = b*Hh + h;
    int n0 = blockIdx.y * 128;
    int wrow = warp * 16;
    int n_lo = n0 + wrow + qr;

    const __nv_bfloat16* khp = g_khi + (size_t)bh*Mm*64;
    const __nv_bfloat16* klp = g_klo + (size_t)bh*Mm*64;
    const __nv_bfloat16* vhp = g_vhi + (size_t)bh*64*Mm;
    const __nv_bfloat16* vlp = g_vlo + (size_t)bh*64*Mm;

    // preload Q fragments (hi/lo) for this warp's 16 rows, all 64 dh
    uint32_t q_hi[4][4], q_lo[4][4];
    {
        const __nv_bfloat16* qh = g_qhi + ((size_t)bh*Nn + n_lo)*64;
        const __nv_bfloat16* ql = g_qlo + ((size_t)bh*Nn + n_lo)*64;
#pragma unroll
        for (int ks = 0; ks < 4; ks++) {
            int kb = ks*16 + qc2;
            q_hi[ks][0] = *(const uint32_t*)&qh[kb];
            q_hi[ks][1] = *(const uint32_t*)&qh[8*64 + kb];
            q_hi[ks][2] = *(const uint32_t*)&qh[kb + 8];
            q_hi[ks][3] = *(const uint32_t*)&qh[8*64 + kb + 8];
            q_lo[ks][0] = *(const uint32_t*)&ql[kb];
            q_lo[ks][1] = *(const uint32_t*)&ql[8*64 + kb];
            q_lo[ks][2] = *(const uint32_t*)&ql[kb + 8];
            q_lo[ks][3] = *(const uint32_t*)&ql[8*64 + kb + 8];
        }
    }

    float hid[8][4];
#pragma unroll
    for (int nf = 0; nf < 8; nf++)
#pragma unroll
        for (int e = 0; e < 4; e++) hid[nf][e] = 0.0f;
    float rs_lo = 0.0f, rs_hi = 0.0f;

    size_t af_lo_row = ((size_t)b*Nn + n_lo)*Mm;
    size_t af_hi_row = af_lo_row + (size_t)8*Mm;
    size_t at_lo_row = ((size_t)bh*Nn + n_lo)*Mm;
    size_t at_hi_row = at_lo_row + (size_t)8*Mm;

    // ---- async stage of one 64-m chunk into buffer `buf` ----
    auto stage = [&](int buf, int m0) {
#pragma unroll
        for (int i = tid; i < 512; i += 256) {
            int r = i >> 3, c8 = (i & 7) * 8;
            cpa16(&Kh[buf][r][c8],  khp + (size_t)(m0 + r)*64 + c8);
            cpa16(&Kl[buf][r][c8],  klp + (size_t)(m0 + r)*64 + c8);
            cpa16(&Vth[buf][r][c8], vhp + (size_t)r*Mm + m0 + c8);
            cpa16(&Vtl[buf][r][c8], vlp + (size_t)r*Mm + m0 + c8);
        }
        if (tid < 16) cpa16(&s_km[buf*64 + tid*4], kmask + b*Mm + m0 + tid*4);
        asm volatile("cp.async.commit_group;" ::: "memory");
    };

    stage(0, 0);

#pragma unroll 1
    for (int c = 0; c < 32; c++) {
        int buf = c & 1;
        int m0 = c * 64;
        if (c + 1 < 32) {
            stage(buf ^ 1, m0 + 64);
            asm volatile("cp.async.wait_group 1;" ::: "memory");
        } else {
            asm volatile("cp.async.wait_group 0;" ::: "memory");
        }
        __syncthreads();

        // QK^T: s (16 x 64) fp32, 3-way bf16 split
        float sc[8][4];
#pragma unroll
        for (int nf = 0; nf < 8; nf++)
#pragma unroll
            for (int e = 0; e < 4; e++) sc[nf][e] = 0.0f;
#pragma unroll
        for (int ks = 0; ks < 4; ks++) {
            int kb = ks*16 + qc2;
#pragma unroll
            for (int nf = 0; nf < 8; nf++) {
                int mc = nf*8 + qr;
                uint32_t bhh[2], bll[2];
                bhh[0] = *(const uint32_t*)&Kh[buf][mc][kb];
                bhh[1] = *(const uint32_t*)&Kh[buf][mc][kb+8];
                bll[0] = *(const uint32_t*)&Kl[buf][mc][kb];
                bll[1] = *(const uint32_t*)&Kl[buf][mc][kb+8];
                mma_bf16(sc[nf], q_hi[ks], bhh);
                mma_bf16(sc[nf], q_hi[ks], bll);
                mma_bf16(sc[nf], q_lo[ks], bhh);
            }
        }

        // epilogue: p = mask ? 0 : 2^(s*af)  (kw, 1/8, log2e folded into K/Q)
        uint32_t pa_hi[4][4], pa_lo[4][4];
#pragma unroll
        for (int nf = 0; nf < 8; nf++) {
            int ml = nf*8 + qc2;
            float2 afl = *(const float2*)&af[af_lo_row + m0 + ml];
            float2 afh = *(const float2*)&af[af_hi_row + m0 + ml];
            int2 aml = *(const int2*)&amask[af_lo_row + m0 + ml];
            int2 amh = *(const int2*)&amask[af_hi_row + m0 + ml];
            int km0 = s_km[buf*64 + ml], km1 = s_km[buf*64 + ml + 1];
            float p0 = (km0 | aml.x) ? 0.0f : ex2f(sc[nf][0] * afl.x);
            float p1 = (km1 | aml.y) ? 0.0f : ex2f(sc[nf][1] * afl.y);
            float p2 = (km0 | amh.x) ? 0.0f : ex2f(sc[nf][2] * afh.x);
            float p3 = (km1 | amh.y) ? 0.0f : ex2f(sc[nf][3] * afh.y);
            rs_lo += p0 + p1;
            rs_hi += p2 + p3;
            *(float2*)&out_attn[at_lo_row + m0 + ml] = make_float2(p0, p1);
            *(float2*)&out_attn[at_hi_row + m0 + ml] = make_float2(p2, p3);
            __nv_bfloat16 h0,l0,h1,l1,h2,l2,h3,l3;
            split2(p0,h0,l0); split2(p1,h1,l1); split2(p2,h2,l2); split2(p3,h3,l3);
            int ks = nf >> 1, hf = (nf & 1) * 2;
            pa_hi[ks][hf+0] = pk2(h0, h1);
            pa_hi[ks][hf+1] = pk2(h2, h3);
            pa_lo[ks][hf+0] = pk2(l0, l1);
            pa_lo[ks][hf+1] = pk2(l2, l3);
        }

        // AV: hidden += p @ V (3-way split), V from transposed smem
#pragma unroll
        for (int ks = 0; ks < 4; ks++) {
            int mr = ks*16 + qc2;
#pragma unroll
            for (int nf = 0; nf < 8; nf++) {
                int dc = nf*8 + qr;
                uint32_t bhh[2], bll[2];
                bhh[0] = *(const uint32_t*)&Vth[buf][dc][mr];
                bhh[1] = *(const uint32_t*)&Vth[buf][dc][mr+8];
                bll[0] = *(const uint32_t*)&Vtl[buf][dc][mr];
                bll[1] = *(const uint32_t*)&Vtl[buf][dc][mr+8];
                mma_bf16(hid[nf], pa_hi[ks], bhh);
                mma_bf16(hid[nf], pa_hi[ks], bll);
                mma_bf16(hid[nf], pa_lo[ks], bhh);
            }
        }
        __syncthreads();   // compute on `buf` done before stage(c+1) overwrites it next iter
    }

    // rowsum reduce across the quad, write inverse, write normalized hidden
    rs_lo += __shfl_xor_sync(0xffffffffu, rs_lo, 1);
    rs_lo += __shfl_xor_sync(0xffffffffu, rs_lo, 2);
    rs_hi += __shfl_xor_sync(0xffffffffu, rs_hi, 1);
    rs_hi += __shfl_xor_sync(0xffffffffu, rs_hi, 2);
    float inv_lo = 1.0f / rs_lo;
    float inv_hi = 1.0f / rs_hi;
    if ((lane & 3) == 0) {
        g_inv[(size_t)bh*Nn + n_lo]     = inv_lo;
        g_inv[(size_t)bh*Nn + n_lo + 8] = inv_hi;
    }
#pragma unroll
    for (int nf = 0; nf < 8; nf++) {
        int d = nf*8 + qc2;
        size_t o_lo = ((size_t)b*Nn + n_lo)*Cc + h*64 + d;
        size_t o_hi = o_lo + (size_t)8*Cc;
        *(float2*)&out_hidden[o_lo] = make_float2(hid[nf][0]*inv_lo, hid[nf][1]*inv_lo);
        *(float2*)&out_hidden[o_hi] = make_float2(hid[nf][2]*inv_hi, hid[nf][3]*inv_hi);
    }
}

// ---------------- K3: normalize attn in place ----------------
__global__ __launch_bounds__(256) void norm_kernel(float4* __restrict__ attn4) {
    int i = blockIdx.x * 256 + threadIdx.x;     // 33,554,432 float4s total
    float4 v = attn4[i];
    float inv = g_inv[i >> 9];                  // 512 float4 per (b,h,n) row
    v.x *= inv; v.y *= inv; v.z *= inv; v.w *= inv;
    attn4[i] = v;
}

// ---------------- launch ----------------
extern "C" void kernel_launch(void* const* d_in, const int* in_sizes, int n_in,
                              void* d_out, int out_size) {
    const float* xq    = (const float*)d_in[0];
    const float* xk    = (const float*)d_in[1];
    const float* xv    = (const float*)d_in[2];
    const float* kw    = (const float*)d_in[3];
    const int*   kmask = (const int*)d_in[4];
    const float* af    = (const float*)d_in[5];
    const int*   amask = (const int*)d_in[6];
    const float* Wq    = (const float*)d_in[7];
    const float* bq    = (const float*)d_in[8];
    const float* Wk    = (const float*)d_in[9];
    const float* bk    = (const float*)d_in[10];
    const float* Wv    = (const float*)d_in[11];
    const float* bv    = (const float*)d_in[12];

    float* out_hidden = (float*)d_out;
    float* out_attn   = out_hidden + (size_t)Bb*Nn*Cc;

    const int attn_smem = 8*TILE_B + 2*64*(int)sizeof(int);   // 74,240 B
    cudaFuncSetAttribute(attn_kernel, cudaFuncAttributeMaxDynamicSharedMemorySize, attn_smem);

    proj_kernel<<<dim3(64, 8, 3), 256>>>(xq, xk, xv, Wq, bq, Wk, bk, Wv, bv, kw);
    attn_kernel<<<dim3(8, 16, 4), 256, attn_smem>>>(kmask, af, amask, out_hidden, out_attn);
    norm_kernel<<<131072, 256>>>((float4*)out_attn);
}

// round 11
// speedup vs baseline: 1.7093x; 1.0260x over previous
#include <cuda_runtime.h>
#include <cuda_bf16.h>
#include <stdint.h>

#define Bb 4
#define Nn 2048
#define Mm 2048
#define Cc 512
#define Hh 8
#define DHd 64
#define LOG2E 1.4426950408889634f

// ---------------- static scratch (no allocations allowed) ----------------
__device__ __nv_bfloat16 g_qhi[Bb*Hh*Nn*DHd];   // [bh][n][dh], pre-scaled by 1/8
__device__ __nv_bfloat16 g_qlo[Bb*Hh*Nn*DHd];
__device__ __nv_bfloat16 g_khi[Bb*Hh*Mm*DHd];   // [bh][m][dh], pre-scaled by kw*log2e
__device__ __nv_bfloat16 g_klo[Bb*Hh*Mm*DHd];
__device__ __nv_bfloat16 g_vhi[Bb*Hh*DHd*Mm];   // TRANSPOSED: [bh][dh][m]
__device__ __nv_bfloat16 g_vlo[Bb*Hh*DHd*Mm];
__device__ float        g_inv[Bb*Hh*Nn];        // 1/rowsum

// ---------------- helpers ----------------
__device__ __forceinline__ void mma_bf16(float c[4], const uint32_t a[4], const uint32_t b[2]) {
    asm volatile(
        "mma.sync.aligned.m16n8k16.row.col.f32.bf16.bf16.f32 "
        "{%0,%1,%2,%3}, {%4,%5,%6,%7}, {%8,%9}, {%0,%1,%2,%3};\n"
        : "+f"(c[0]), "+f"(c[1]), "+f"(c[2]), "+f"(c[3])
        : "r"(a[0]), "r"(a[1]), "r"(a[2]), "r"(a[3]), "r"(b[0]), "r"(b[1]));
}

__device__ __forceinline__ void split2(float x, __nv_bfloat16 &hi, __nv_bfloat16 &lo) {
    hi = __float2bfloat16_rn(x);
    lo = __float2bfloat16_rn(x - __bfloat162float(hi));
}

__device__ __forceinline__ uint32_t pk2(__nv_bfloat16 a, __nv_bfloat16 b) {
    return (uint32_t)__bfloat16_as_ushort(a) | ((uint32_t)__bfloat16_as_ushort(b) << 16);
}

// guaranteed MUFU.EX2
__device__ __forceinline__ float ex2f(float x) {
    float r;
    asm("ex2.approx.ftz.f32 %0, %1;" : "=f"(r) : "f"(x));
    return r;
}

// 16B async copy gmem -> smem (LDGSTS)
__device__ __forceinline__ void cpa16(void* smem, const void* gmem) {
    uint32_t s = (uint32_t)__cvta_generic_to_shared(smem);
    asm volatile("cp.async.cg.shared.global [%0], [%1], 16;" :: "r"(s), "l"(gmem));
}

// ---------------- K1: fused projections (X@W + b), bf16-split mma ----------------
// grid: (64, 8, 3)  block: 256
__global__ __launch_bounds__(256) void proj_kernel(
    const float* __restrict__ xq, const float* __restrict__ xk, const float* __restrict__ xv,
    const float* __restrict__ Wq, const float* __restrict__ bq,
    const float* __restrict__ Wk, const float* __restrict__ bk,
    const float* __restrict__ Wv, const float* __restrict__ bv,
    const float* __restrict__ kw)
{
    const float* X; const float* W; const float* bias;
    __nv_bfloat16 *Ohi, *Olo;
    int z = blockIdx.z;
    if (z == 0)      { X = xq; W = Wq; bias = bq; Ohi = g_qhi; Olo = g_qlo; }
    else if (z == 1) { X = xk; W = Wk; bias = bk; Ohi = g_khi; Olo = g_klo; }
    else             { X = xv; W = Wv; bias = bv; Ohi = g_vhi; Olo = g_vlo; }

    __shared__ __nv_bfloat16 Ahi[128][40], Alo[128][40];   // [row][k], k-chunk 32, pad 8
    __shared__ __nv_bfloat16 Bshi[64][40], Bslo[64][40];   // [col][k] transposed

    int tid = threadIdx.x, lane = tid & 31, warp = tid >> 5;
    int row0 = blockIdx.x * 128;
    int col0 = blockIdx.y * 64;
    int wr = (warp >> 1) * 32, wc = (warp & 1) * 32;
    int qr = lane >> 2, qc2 = (lane & 3) * 2;

    float acc[2][4][4];
#pragma unroll
    for (int m = 0; m < 2; m++)
#pragma unroll
        for (int n = 0; n < 4; n++)
#pragma unroll
            for (int e = 0; e < 4; e++) acc[m][n][e] = 0.0f;

    for (int kc = 0; kc < Cc; kc += 32) {
#pragma unroll
        for (int i = tid; i < 128*8; i += 256) {
            int r = i >> 3, c4 = (i & 7) * 4;
            float4 v = *(const float4*)&X[(size_t)(row0 + r)*Cc + kc + c4];
            __nv_bfloat16 h0,l0,h1,l1,h2,l2,h3,l3;
            split2(v.x, h0, l0); split2(v.y, h1, l1);
            split2(v.z, h2, l2); split2(v.w, h3, l3);
            uint2 th; th.x = pk2(h0,h1); th.y = pk2(h2,h3);
            uint2 tl; tl.x = pk2(l0,l1); tl.y = pk2(l2,l3);
            *(uint2*)&Ahi[r][c4] = th;
            *(uint2*)&Alo[r][c4] = tl;
        }
#pragma unroll
        for (int it = 0; it < 2; it++) {
            int slot = tid + it*256;
            int col = slot & 63, kk0 = (slot >> 6) * 4;
            __nv_bfloat16 h0,l0,h1,l1,h2,l2,h3,l3;
            float v0 = W[(size_t)(kc+kk0+0)*Cc + col0 + col];
            float v1 = W[(size_t)(kc+kk0+1)*Cc + col0 + col];
            float v2 = W[(size_t)(kc+kk0+2)*Cc + col0 + col];
            float v3 = W[(size_t)(kc+kk0+3)*Cc + col0 + col];
            split2(v0, h0, l0); split2(v1, h1, l1);
            split2(v2, h2, l2); split2(v3, h3, l3);
            uint2 th; th.x = pk2(h0,h1); th.y = pk2(h2,h3);
            uint2 tl; tl.x = pk2(l0,l1); tl.y = pk2(l2,l3);
            *(uint2*)&Bshi[col][kk0] = th;
            *(uint2*)&Bslo[col][kk0] = tl;
        }
        __syncthreads();
#pragma unroll
        for (int ks = 0; ks < 2; ks++) {
            int kb = ks*16 + qc2;
            uint32_t a_hi[2][4], a_lo[2][4];
#pragma unroll
            for (int m = 0; m < 2; m++) {
                int r = wr + m*16 + qr;
                a_hi[m][0] = *(const uint32_t*)&Ahi[r][kb];
                a_hi[m][1] = *(const uint32_t*)&Ahi[r+8][kb];
                a_hi[m][2] = *(const uint32_t*)&Ahi[r][kb+8];
                a_hi[m][3] = *(const uint32_t*)&Ahi[r+8][kb+8];
                a_lo[m][0] = *(const uint32_t*)&Alo[r][kb];
                a_lo[m][1] = *(const uint32_t*)&Alo[r+8][kb];
                a_lo[m][2] = *(const uint32_t*)&Alo[r][kb+8];
                a_lo[m][3] = *(const uint32_t*)&Alo[r+8][kb+8];
            }
#pragma unroll
            for (int nf = 0; nf < 4; nf++) {
                int cn = wc + nf*8 + qr;
                uint32_t b_hi[2], b_lo[2];
                b_hi[0] = *(const uint32_t*)&Bshi[cn][kb];
                b_hi[1] = *(const uint32_t*)&Bshi[cn][kb+8];
                b_lo[0] = *(const uint32_t*)&Bslo[cn][kb];
                b_lo[1] = *(const uint32_t*)&Bslo[cn][kb+8];
#pragma unroll
                for (int m = 0; m < 2; m++) {
                    mma_bf16(acc[m][nf], a_hi[m], b_hi);
                    mma_bf16(acc[m][nf], a_hi[m], b_lo);
                    mma_bf16(acc[m][nf], a_lo[m], b_hi);
                }
            }
        }
        __syncthreads();
    }

    int h = blockIdx.y;
#pragma unroll
    for (int m = 0; m < 2; m++) {
#pragma unroll
        for (int e = 0; e < 2; e++) {
            int rg = row0 + wr + m*16 + qr + e*8;
            int bb = rg >> 11, sq = rg & 2047;
            float rsc;
            if (z == 0)      rsc = 0.125f;
            else if (z == 1) rsc = kw[bb*Mm + sq] * LOG2E;
            else             rsc = 1.0f;
#pragma unroll
            for (int nf = 0; nf < 4; nf++) {
                int d = wc + nf*8 + qc2;
                float v0 = (acc[m][nf][e*2+0] + bias[col0+d])   * rsc;
                float v1 = (acc[m][nf][e*2+1] + bias[col0+d+1]) * rsc;
                __nv_bfloat16 h0, l0, h1, l1;
                split2(v0, h0, l0); split2(v1, h1, l1);
                if (z != 2) {
                    size_t o = ((size_t)((bb*Hh + h)*2048 + sq))*64 + d;
                    __nv_bfloat162 th; th.x = h0; th.y = h1;
                    __nv_bfloat162 tl; tl.x = l0; tl.y = l1;
                    *(__nv_bfloat162*)&Ohi[o] = th;
                    *(__nv_bfloat162*)&Olo[o] = tl;
                } else {
                    size_t o = ((size_t)((bb*Hh + h)*64 + d))*2048 + sq;
                    Ohi[o] = h0; Ohi[o + 2048] = h1;
                    Olo[o] = l0; Olo[o + 2048] = l1;
                }
            }
        }
    }
}

// ---------------- K2: fused attention, 3-stage cp.async pipeline ------
// grid: (h 8, n-blocks 16, b 4)  block 256 (8 warps x 16 rows = 128 q rows).
// Head fastest in grid -> af/amask L2-shared across the 8 CTAs of a (b,nblk).
// 3 smem buffers, stage c+2 while computing c => ONE barrier per chunk.
#define TILE_B (64*72*2)        // one [64][72] bf16 buffer = 9216 B
#define NSTG 3
__global__ __launch_bounds__(256) void attn_kernel(
    const int* __restrict__ kmask, const float* __restrict__ af,
    const int* __restrict__ amask,
    float* __restrict__ out_hidden, float* __restrict__ out_attn)
{
    extern __shared__ char dsm[];
    __nv_bfloat16 (*Kh)[64][72]  = (__nv_bfloat16(*)[64][72])(dsm);
    __nv_bfloat16 (*Kl)[64][72]  = (__nv_bfloat16(*)[64][72])(dsm + NSTG*TILE_B);
    __nv_bfloat16 (*Vth)[64][72] = (__nv_bfloat16(*)[64][72])(dsm + 2*NSTG*TILE_B);
    __nv_bfloat16 (*Vtl)[64][72] = (__nv_bfloat16(*)[64][72])(dsm + 3*NSTG*TILE_B);
    int* s_km = (int*)(dsm + 4*NSTG*TILE_B);      // [NSTG][64]

    int tid = threadIdx.x, lane = tid & 31, warp = tid >> 5;
    int qr = lane >> 2, qc2 = (lane & 3) * 2;
    int h = blockIdx.x, b = blockIdx.z;
    int bh = b*Hh + h;
    int n0 = blockIdx.y * 128;
    int wrow = warp * 16;
    int n_lo = n0 + wrow + qr;

    const __nv_bfloat16* khp = g_khi + (size_t)bh*Mm*64;
    const __nv_bfloat16* klp = g_klo + (size_t)bh*Mm*64;
    const __nv_bfloat16* vhp = g_vhi + (size_t)bh*64*Mm;
    const __nv_bfloat16* vlp = g_vlo + (size_t)bh*64*Mm;

    // preload Q fragments (hi/lo) for this warp's 16 rows, all 64 dh
    uint32_t q_hi[4][4], q_lo[4][4];
    {
        const __nv_bfloat16* qh = g_qhi + ((size_t)bh*Nn + n_lo)*64;
        const __nv_bfloat16* ql = g_qlo + ((size_t)bh*Nn + n_lo)*64;
#pragma unroll
        for (int ks = 0; ks < 4; ks++) {
            int kb = ks*16 + qc2;
            q_hi[ks][0] = *(const uint32_t*)&qh[kb];
            q_hi[ks][1] = *(const uint32_t*)&qh[8*64 + kb];
            q_hi[ks][2] = *(const uint32_t*)&qh[kb + 8];
            q_hi[ks][3] = *(const uint32_t*)&qh[8*64 + kb + 8];
            q_lo[ks][0] = *(const uint32_t*)&ql[kb];
            q_lo[ks][1] = *(const uint32_t*)&ql[8*64 + kb];
            q_lo[ks][2] = *(const uint32_t*)&ql[kb + 8];
            q_lo[ks][3] = *(const uint32_t*)&ql[8*64 + kb + 8];
        }
    }

    float hid[8][4];
#pragma unroll
    for (int nf = 0; nf < 8; nf++)
#pragma unroll
        for (int e = 0; e < 4; e++) hid[nf][e] = 0.0f;
    float rs_lo = 0.0f, rs_hi = 0.0f;

    size_t af_lo_row = ((size_t)b*Nn + n_lo)*Mm;
    size_t af_hi_row = af_lo_row + (size_t)8*Mm;
    size_t at_lo_row = ((size_t)bh*Nn + n_lo)*Mm;
    size_t at_hi_row = at_lo_row + (size_t)8*Mm;

    // ---- async stage of one 64-m chunk into buffer `buf` ----
    auto stage = [&](int buf, int m0) {
#pragma unroll
        for (int i = tid; i < 512; i += 256) {
            int r = i >> 3, c8 = (i & 7) * 8;
            cpa16(&Kh[buf][r][c8],  khp + (size_t)(m0 + r)*64 + c8);
            cpa16(&Kl[buf][r][c8],  klp + (size_t)(m0 + r)*64 + c8);
            cpa16(&Vth[buf][r][c8], vhp + (size_t)r*Mm + m0 + c8);
            cpa16(&Vtl[buf][r][c8], vlp + (size_t)r*Mm + m0 + c8);
        }
        if (tid < 16) cpa16(&s_km[buf*64 + tid*4], kmask + b*Mm + m0 + tid*4);
        asm volatile("cp.async.commit_group;" ::: "memory");
    };

    stage(0, 0);
    stage(1, 64);

#pragma unroll 1
    for (int c = 0; c < 32; c++) {
        int buf = c % NSTG;
        int m0 = c * 64;
        if (c + 1 < 32) {
            asm volatile("cp.async.wait_group 1;" ::: "memory");
        } else {
            asm volatile("cp.async.wait_group 0;" ::: "memory");
        }
        __syncthreads();      // single barrier per chunk: protects buf reads AND
                              // makes (c+2)%3 (computed at c-1) safe to restage
        if (c + 2 < 32) stage((c + 2) % NSTG, m0 + 128);

        // prefetch af/amask for this chunk BEFORE the QK MMAs (hide L2 latency)
        float2 pfl[8], pfh[8];
        int2   pml[8], pmh[8];
#pragma unroll
        for (int nf = 0; nf < 8; nf++) {
            int ml = nf*8 + qc2;
            pfl[nf] = *(const float2*)&af[af_lo_row + m0 + ml];
            pfh[nf] = *(const float2*)&af[af_hi_row + m0 + ml];
            pml[nf] = *(const int2*)&amask[af_lo_row + m0 + ml];
            pmh[nf] = *(const int2*)&amask[af_hi_row + m0 + ml];
        }

        // QK^T: s (16 x 64) fp32, 3-way bf16 split
        float sc[8][4];
#pragma unroll
        for (int nf = 0; nf < 8; nf++)
#pragma unroll
            for (int e = 0; e < 4; e++) sc[nf][e] = 0.0f;
#pragma unroll
        for (int ks = 0; ks < 4; ks++) {
            int kb = ks*16 + qc2;
#pragma unroll
            for (int nf = 0; nf < 8; nf++) {
                int mc = nf*8 + qr;
                uint32_t bhh[2], bll[2];
                bhh[0] = *(const uint32_t*)&Kh[buf][mc][kb];
                bhh[1] = *(const uint32_t*)&Kh[buf][mc][kb+8];
                bll[0] = *(const uint32_t*)&Kl[buf][mc][kb];
                bll[1] = *(const uint32_t*)&Kl[buf][mc][kb+8];
                mma_bf16(sc[nf], q_hi[ks], bhh);
                mma_bf16(sc[nf], q_hi[ks], bll);
                mma_bf16(sc[nf], q_lo[ks], bhh);
            }
        }

        // epilogue: p = mask ? 0 : 2^(s*af)  (kw, 1/8, log2e folded into K/Q)
        uint32_t pa_hi[4][4], pa_lo[4][4];
#pragma unroll
        for (int nf = 0; nf < 8; nf++) {
            int ml = nf*8 + qc2;
            int km0 = s_km[buf*64 + ml], km1 = s_km[buf*64 + ml + 1];
            float p0 = (km0 | pml[nf].x) ? 0.0f : ex2f(sc[nf][0] * pfl[nf].x);
            float p1 = (km1 | pml[nf].y) ? 0.0f : ex2f(sc[nf][1] * pfl[nf].y);
            float p2 = (km0 | pmh[nf].x) ? 0.0f : ex2f(sc[nf][2] * pfh[nf].x);
            float p3 = (km1 | pmh[nf].y) ? 0.0f : ex2f(sc[nf][3] * pfh[nf].y);
            rs_lo += p0 + p1;
            rs_hi += p2 + p3;
            *(float2*)&out_attn[at_lo_row + m0 + ml] = make_float2(p0, p1);
            *(float2*)&out_attn[at_hi_row + m0 + ml] = make_float2(p2, p3);
            __nv_bfloat16 h0,l0,h1,l1,h2,l2,h3,l3;
            split2(p0,h0,l0); split2(p1,h1,l1); split2(p2,h2,l2); split2(p3,h3,l3);
            int ks = nf >> 1, hf = (nf & 1) * 2;
            pa_hi[ks][hf+0] = pk2(h0, h1);
            pa_hi[ks][hf+1] = pk2(h2, h3);
            pa_lo[ks][hf+0] = pk2(l0, l1);
            pa_lo[ks][hf+1] = pk2(l2, l3);
        }

        // AV: hidden += p @ V (3-way split), V from transposed smem
#pragma unroll
        for (int ks = 0; ks < 4; ks++) {
            int mr = ks*16 + qc2;
#pragma unroll
            for (int nf = 0; nf < 8; nf++) {
                int dc = nf*8 + qr;
                uint32_t bhh[2], bll[2];
                bhh[0] = *(const uint32_t*)&Vth[buf][dc][mr];
                bhh[1] = *(const uint32_t*)&Vth[buf][dc][mr+8];
                bll[0] = *(const uint32_t*)&Vtl[buf][dc][mr];
                bll[1] = *(const uint32_t*)&Vtl[buf][dc][mr+8];
                mma_bf16(hid[nf], pa_hi[ks], bhh);
                mma_bf16(hid[nf], pa_hi[ks], bll);
                mma_bf16(hid[nf], pa_lo[ks], bhh);
            }
        }
    }

    // rowsum reduce across the quad, write inverse, write normalized hidden
    rs_lo += __shfl_xor_sync(0xffffffffu, rs_lo, 1);
    rs_lo += __shfl_xor_sync(0xffffffffu, rs_lo, 2);
    rs_hi += __shfl_xor_sync(0xffffffffu, rs_hi, 1);
    rs_hi += __shfl_xor_sync(0xffffffffu, rs_hi, 2);
    float inv_lo = 1.0f / rs_lo;
    float inv_hi = 1.0f / rs_hi;
    if ((lane & 3) == 0) {
        g_inv[(size_t)bh*Nn + n_lo]     = inv_lo;
        g_inv[(size_t)bh*Nn + n_lo + 8] = inv_hi;
    }
#pragma unroll
    for (int nf = 0; nf < 8; nf++) {
        int d = nf*8 + qc2;
        size_t o_lo = ((size_t)b*Nn + n_lo)*Cc + h*64 + d;
        size_t o_hi = o_lo + (size_t)8*Cc;
        *(float2*)&out_hidden[o_lo] = make_float2(hid[nf][0]*inv_lo, hid[nf][1]*inv_lo);
        *(float2*)&out_hidden[o_hi] = make_float2(hid[nf][2]*inv_hi, hid[nf][3]*inv_hi);
    }
}

// ---------------- K3: normalize attn in place ----------------
__global__ __launch_bounds__(256) void norm_kernel(float4* __restrict__ attn4) {
    int i = blockIdx.x * 256 + threadIdx.x;     // 33,554,432 float4s total
    float4 v = attn4[i];
    float inv = g_inv[i >> 9];                  // 512 float4 per (b,h,n) row
    v.x *= inv; v.y *= inv; v.z *= inv; v.w *= inv;
    attn4[i] = v;
}

// ---------------- launch ----------------
extern "C" void kernel_launch(void* const* d_in, const int* in_sizes, int n_in,
                              void* d_out, int out_size) {
    const float* xq    = (const float*)d_in[0];
    const float* xk    = (const float*)d_in[1];
    const float* xv    = (const float*)d_in[2];
    const float* kw    = (const float*)d_in[3];
    const int*   kmask = (const int*)d_in[4];
    const float* af    = (const float*)d_in[5];
    const int*   amask = (const int*)d_in[6];
    const float* Wq    = (const float*)d_in[7];
    const float* bq    = (const float*)d_in[8];
    const float* Wk    = (const float*)d_in[9];
    const float* bk    = (const float*)d_in[10];
    const float* Wv    = (const float*)d_in[11];
    const float* bv    = (const float*)d_in[12];

    float* out_hidden = (float*)d_out;
    float* out_attn   = out_hidden + (size_t)Bb*Nn*Cc;

    const int attn_smem = 4*NSTG*TILE_B + NSTG*64*(int)sizeof(int);   // 111,360 B
    cudaFuncSetAttribute(attn_kernel, cudaFuncAttributeMaxDynamicSharedMemorySize, attn_smem);

    proj_kernel<<<dim3(64, 8, 3), 256>>>(xq, xk, xv, Wq, bq, Wk, bk, Wv, bv, kw);
    attn_kernel<<<dim3(8, 16, 4), 256, attn_smem>>>(kmask, af, amask, out_hidden, out_attn);
    norm_kernel<<<131072, 256>>>((float4*)out_attn);
}

// round 12
// speedup vs baseline: 2.0123x; 1.1773x over previous
#include <cuda_runtime.h>
#include <cuda_bf16.h>
#include <stdint.h>

#define Bb 4
#define Nn 2048
#define Mm 2048
#define Cc 512
#define Hh 8
#define DHd 64
#define LOG2E 1.4426950408889634f

// ---------------- static scratch (no allocations allowed) ----------------
__device__ __nv_bfloat16 g_qhi[Bb*Hh*Nn*DHd];   // [bh][n][dh], pre-scaled by 1/8
__device__ __nv_bfloat16 g_qlo[Bb*Hh*Nn*DHd];
__device__ __nv_bfloat16 g_khi[Bb*Hh*Mm*DHd];   // [bh][m][dh], pre-scaled by kw*log2e
__device__ __nv_bfloat16 g_klo[Bb*Hh*Mm*DHd];
__device__ __nv_bfloat16 g_vhi[Bb*Hh*DHd*Mm];   // TRANSPOSED: [bh][dh][m]
__device__ __nv_bfloat16 g_vlo[Bb*Hh*DHd*Mm];
__device__ float        g_inv[Bb*Hh*Nn];        // 1/rowsum

// ---------------- helpers ----------------
__device__ __forceinline__ void mma_bf16(float c[4], const uint32_t a[4], const uint32_t b[2]) {
    asm volatile(
        "mma.sync.aligned.m16n8k16.row.col.f32.bf16.bf16.f32 "
        "{%0,%1,%2,%3}, {%4,%5,%6,%7}, {%8,%9}, {%0,%1,%2,%3};\n"
        : "+f"(c[0]), "+f"(c[1]), "+f"(c[2]), "+f"(c[3])
        : "r"(a[0]), "r"(a[1]), "r"(a[2]), "r"(a[3]), "r"(b[0]), "r"(b[1]));
}

__device__ __forceinline__ void split2(float x, __nv_bfloat16 &hi, __nv_bfloat16 &lo) {
    hi = __float2bfloat16_rn(x);
    lo = __float2bfloat16_rn(x - __bfloat162float(hi));
}

__device__ __forceinline__ uint32_t pk2(__nv_bfloat16 a, __nv_bfloat16 b) {
    return (uint32_t)__bfloat16_as_ushort(a) | ((uint32_t)__bfloat16_as_ushort(b) << 16);
}

// guaranteed MUFU.EX2
__device__ __forceinline__ float ex2f(float x) {
    float r;
    asm("ex2.approx.ftz.f32 %0, %1;" : "=f"(r) : "f"(x));
    return r;
}

// 16B async copy gmem -> smem (LDGSTS)
__device__ __forceinline__ void cpa16(void* smem, const void* gmem) {
    uint32_t s = (uint32_t)__cvta_generic_to_shared(smem);
    asm volatile("cp.async.cg.shared.global [%0], [%1], 16;" :: "r"(s), "l"(gmem));
}

// ---------------- K1: fused projections (X@W + b), bf16-split mma ----------------
// grid: (64, 8, 3)  block: 256
__global__ __launch_bounds__(256) void proj_kernel(
    const float* __restrict__ xq, const float* __restrict__ xk, const float* __restrict__ xv,
    const float* __restrict__ Wq, const float* __restrict__ bq,
    const float* __restrict__ Wk, const float* __restrict__ bk,
    const float* __restrict__ Wv, const float* __restrict__ bv,
    const float* __restrict__ kw)
{
    const float* X; const float* W; const float* bias;
    __nv_bfloat16 *Ohi, *Olo;
    int z = blockIdx.z;
    if (z == 0)      { X = xq; W = Wq; bias = bq; Ohi = g_qhi; Olo = g_qlo; }
    else if (z == 1) { X = xk; W = Wk; bias = bk; Ohi = g_khi; Olo = g_klo; }
    else             { X = xv; W = Wv; bias = bv; Ohi = g_vhi; Olo = g_vlo; }

    __shared__ __nv_bfloat16 Ahi[128][40], Alo[128][40];   // [row][k], k-chunk 32, pad 8
    __shared__ __nv_bfloat16 Bshi[64][40], Bslo[64][40];   // [col][k] transposed

    int tid = threadIdx.x, lane = tid & 31, warp = tid >> 5;
    int row0 = blockIdx.x * 128;
    int col0 = blockIdx.y * 64;
    int wr = (warp >> 1) * 32, wc = (warp & 1) * 32;
    int qr = lane >> 2, qc2 = (lane & 3) * 2;

    float acc[2][4][4];
#pragma unroll
    for (int m = 0; m < 2; m++)
#pragma unroll
        for (int n = 0; n < 4; n++)
#pragma unroll
            for (int e = 0; e < 4; e++) acc[m][n][e] = 0.0f;

    for (int kc = 0; kc < Cc; kc += 32) {
#pragma unroll
        for (int i = tid; i < 128*8; i += 256) {
            int r = i >> 3, c4 = (i & 7) * 4;
            float4 v = *(const float4*)&X[(size_t)(row0 + r)*Cc + kc + c4];
            __nv_bfloat16 h0,l0,h1,l1,h2,l2,h3,l3;
            split2(v.x, h0, l0); split2(v.y, h1, l1);
            split2(v.z, h2, l2); split2(v.w, h3, l3);
            uint2 th; th.x = pk2(h0,h1); th.y = pk2(h2,h3);
            uint2 tl; tl.x = pk2(l0,l1); tl.y = pk2(l2,l3);
            *(uint2*)&Ahi[r][c4] = th;
            *(uint2*)&Alo[r][c4] = tl;
        }
#pragma unroll
        for (int it = 0; it < 2; it++) {
            int slot = tid + it*256;
            int col = slot & 63, kk0 = (slot >> 6) * 4;
            __nv_bfloat16 h0,l0,h1,l1,h2,l2,h3,l3;
            float v0 = W[(size_t)(kc+kk0+0)*Cc + col0 + col];
            float v1 = W[(size_t)(kc+kk0+1)*Cc + col0 + col];
            float v2 = W[(size_t)(kc+kk0+2)*Cc + col0 + col];
            float v3 = W[(size_t)(kc+kk0+3)*Cc + col0 + col];
            split2(v0, h0, l0); split2(v1, h1, l1);
            split2(v2, h2, l2); split2(v3, h3, l3);
            uint2 th; th.x = pk2(h0,h1); th.y = pk2(h2,h3);
            uint2 tl; tl.x = pk2(l0,l1); tl.y = pk2(l2,l3);
            *(uint2*)&Bshi[col][kk0] = th;
            *(uint2*)&Bslo[col][kk0] = tl;
        }
        __syncthreads();
#pragma unroll
        for (int ks = 0; ks < 2; ks++) {
            int kb = ks*16 + qc2;
            uint32_t a_hi[2][4], a_lo[2][4];
#pragma unroll
            for (int m = 0; m < 2; m++) {
                int r = wr + m*16 + qr;
                a_hi[m][0] = *(const uint32_t*)&Ahi[r][kb];
                a_hi[m][1] = *(const uint32_t*)&Ahi[r+8][kb];
                a_hi[m][2] = *(const uint32_t*)&Ahi[r][kb+8];
                a_hi[m][3] = *(const uint32_t*)&Ahi[r+8][kb+8];
                a_lo[m][0] = *(const uint32_t*)&Alo[r][kb];
                a_lo[m][1] = *(const uint32_t*)&Alo[r+8][kb];
                a_lo[m][2] = *(const uint32_t*)&Alo[r][kb+8];
                a_lo[m][3] = *(const uint32_t*)&Alo[r+8][kb+8];
            }
#pragma unroll
            for (int nf = 0; nf < 4; nf++) {
                int cn = wc + nf*8 + qr;
                uint32_t b_hi[2], b_lo[2];
                b_hi[0] = *(const uint32_t*)&Bshi[cn][kb];
                b_hi[1] = *(const uint32_t*)&Bshi[cn][kb+8];
                b_lo[0] = *(const uint32_t*)&Bslo[cn][kb];
                b_lo[1] = *(const uint32_t*)&Bslo[cn][kb+8];
#pragma unroll
                for (int m = 0; m < 2; m++) {
                    mma_bf16(acc[m][nf], a_hi[m], b_hi);
                    mma_bf16(acc[m][nf], a_hi[m], b_lo);
                    mma_bf16(acc[m][nf], a_lo[m], b_hi);
                }
            }
        }
        __syncthreads();
    }

    int h = blockIdx.y;
#pragma unroll
    for (int m = 0; m < 2; m++) {
#pragma unroll
        for (int e = 0; e < 2; e++) {
            int rg = row0 + wr + m*16 + qr + e*8;
            int bb = rg >> 11, sq = rg & 2047;
            float rsc;
            if (z == 0)      rsc = 0.125f;
            else if (z == 1) rsc = kw[bb*Mm + sq] * LOG2E;
            else             rsc = 1.0f;
#pragma unroll
            for (int nf = 0; nf < 4; nf++) {
                int d = wc + nf*8 + qc2;
                float v0 = (acc[m][nf][e*2+0] + bias[col0+d])   * rsc;
                float v1 = (acc[m][nf][e*2+1] + bias[col0+d+1]) * rsc;
                __nv_bfloat16 h0, l0, h1, l1;
                split2(v0, h0, l0); split2(v1, h1, l1);
                if (z != 2) {
                    size_t o = ((size_t)((bb*Hh + h)*2048 + sq))*64 + d;
                    __nv_bfloat162 th; th.x = h0; th.y = h1;
                    __nv_bfloat162 tl; tl.x = l0; tl.y = l1;
                    *(__nv_bfloat162*)&Ohi[o] = th;
                    *(__nv_bfloat162*)&Olo[o] = tl;
                } else {
                    size_t o = ((size_t)((bb*Hh + h)*64 + d))*2048 + sq;
                    Ohi[o] = h0; Ohi[o + 2048] = h1;
                    Olo[o] = l0; Olo[o + 2048] = l1;
                }
            }
        }
    }
}

// ---------------- K2: fused attention, 128-thread CTAs, 2 CTAs/SM ------
// grid: (h 8, n-blocks 32, b 4) = 1024 CTAs, block 128 (4 warps x 16 rows = 64 q rows).
// Head fastest in grid -> af/amask L2-shared across the 8 CTAs of a (b,nblk).
// 2-stage cp.async pipeline; stage(c+1) issued after the top barrier.
#define TILE_B (64*72*2)        // one [64][72] bf16 buffer = 9216 B
#define NSTG 2
__global__ __launch_bounds__(128) void attn_kernel(
    const int* __restrict__ kmask, const float* __restrict__ af,
    const int* __restrict__ amask,
    float* __restrict__ out_hidden, float* __restrict__ out_attn)
{
    extern __shared__ char dsm[];
    __nv_bfloat16 (*Kh)[64][72]  = (__nv_bfloat16(*)[64][72])(dsm);
    __nv_bfloat16 (*Kl)[64][72]  = (__nv_bfloat16(*)[64][72])(dsm + NSTG*TILE_B);
    __nv_bfloat16 (*Vth)[64][72] = (__nv_bfloat16(*)[64][72])(dsm + 2*NSTG*TILE_B);
    __nv_bfloat16 (*Vtl)[64][72] = (__nv_bfloat16(*)[64][72])(dsm + 3*NSTG*TILE_B);
    int* s_km = (int*)(dsm + 4*NSTG*TILE_B);      // [NSTG][64]

    int tid = threadIdx.x, lane = tid & 31, warp = tid >> 5;
    int qr = lane >> 2, qc2 = (lane & 3) * 2;
    int h = blockIdx.x, b = blockIdx.z;
    int bh = b*Hh + h;
    int n0 = blockIdx.y * 64;
    int wrow = warp * 16;
    int n_lo = n0 + wrow + qr;

    const __nv_bfloat16* khp = g_khi + (size_t)bh*Mm*64;
    const __nv_bfloat16* klp = g_klo + (size_t)bh*Mm*64;
    const __nv_bfloat16* vhp = g_vhi + (size_t)bh*64*Mm;
    const __nv_bfloat16* vlp = g_vlo + (size_t)bh*64*Mm;

    // preload Q fragments (hi/lo) for this warp's 16 rows, all 64 dh
    uint32_t q_hi[4][4], q_lo[4][4];
    {
        const __nv_bfloat16* qh = g_qhi + ((size_t)bh*Nn + n_lo)*64;
        const __nv_bfloat16* ql = g_qlo + ((size_t)bh*Nn + n_lo)*64;
#pragma unroll
        for (int ks = 0; ks < 4; ks++) {
            int kb = ks*16 + qc2;
            q_hi[ks][0] = *(const uint32_t*)&qh[kb];
            q_hi[ks][1] = *(const uint32_t*)&qh[8*64 + kb];
            q_hi[ks][2] = *(const uint32_t*)&qh[kb + 8];
            q_hi[ks][3] = *(const uint32_t*)&qh[8*64 + kb + 8];
            q_lo[ks][0] = *(const uint32_t*)&ql[kb];
            q_lo[ks][1] = *(const uint32_t*)&ql[8*64 + kb];
            q_lo[ks][2] = *(const uint32_t*)&ql[kb + 8];
            q_lo[ks][3] = *(const uint32_t*)&ql[8*64 + kb + 8];
        }
    }

    float hid[8][4];
#pragma unroll
    for (int nf = 0; nf < 8; nf++)
#pragma unroll
        for (int e = 0; e < 4; e++) hid[nf][e] = 0.0f;
    float rs_lo = 0.0f, rs_hi = 0.0f;

    size_t af_lo_row = ((size_t)b*Nn + n_lo)*Mm;
    size_t af_hi_row = af_lo_row + (size_t)8*Mm;
    size_t at_lo_row = ((size_t)bh*Nn + n_lo)*Mm;
    size_t at_hi_row = at_lo_row + (size_t)8*Mm;

    // ---- async stage of one 64-m chunk into buffer `buf` ----
    auto stage = [&](int buf, int m0) {
#pragma unroll
        for (int i = tid; i < 512; i += 128) {
            int r = i >> 3, c8 = (i & 7) * 8;
            cpa16(&Kh[buf][r][c8],  khp + (size_t)(m0 + r)*64 + c8);
            cpa16(&Kl[buf][r][c8],  klp + (size_t)(m0 + r)*64 + c8);
            cpa16(&Vth[buf][r][c8], vhp + (size_t)r*Mm + m0 + c8);
            cpa16(&Vtl[buf][r][c8], vlp + (size_t)r*Mm + m0 + c8);
        }
        if (tid < 16) cpa16(&s_km[buf*64 + tid*4], kmask + b*Mm + m0 + tid*4);
        asm volatile("cp.async.commit_group;" ::: "memory");
    };

    stage(0, 0);

#pragma unroll 1
    for (int c = 0; c < 32; c++) {
        int buf = c & 1;
        int m0 = c * 64;
        asm volatile("cp.async.wait_group 0;" ::: "memory");   // stage(c) done
        __syncthreads();   // all warps finished reading buf (c+1)&1 at iter c-1
        if (c + 1 < 32) stage(buf ^ 1, m0 + 64);

        // prefetch af/amask for this chunk BEFORE the QK MMAs (hide L2 latency)
        float2 pfl[8], pfh[8];
        int2   pml[8], pmh[8];
#pragma unroll
        for (int nf = 0; nf < 8; nf++) {
            int ml = nf*8 + qc2;
            pfl[nf] = *(const float2*)&af[af_lo_row + m0 + ml];
            pfh[nf] = *(const float2*)&af[af_hi_row + m0 + ml];
            pml[nf] = *(const int2*)&amask[af_lo_row + m0 + ml];
            pmh[nf] = *(const int2*)&amask[af_hi_row + m0 + ml];
        }

        // QK^T: s (16 x 64) fp32, 3-way bf16 split
        float sc[8][4];
#pragma unroll
        for (int nf = 0; nf < 8; nf++)
#pragma unroll
            for (int e = 0; e < 4; e++) sc[nf][e] = 0.0f;
#pragma unroll
        for (int ks = 0; ks < 4; ks++) {
            int kb = ks*16 + qc2;
#pragma unroll
            for (int nf = 0; nf < 8; nf++) {
                int mc = nf*8 + qr;
                uint32_t bhh[2], bll[2];
                bhh[0] = *(const uint32_t*)&Kh[buf][mc][kb];
                bhh[1] = *(const uint32_t*)&Kh[buf][mc][kb+8];
                bll[0] = *(const uint32_t*)&Kl[buf][mc][kb];
                bll[1] = *(const uint32_t*)&Kl[buf][mc][kb+8];
                mma_bf16(sc[nf], q_hi[ks], bhh);
                mma_bf16(sc[nf], q_hi[ks], bll);
                mma_bf16(sc[nf], q_lo[ks], bhh);
            }
        }

        // epilogue: p = mask ? 0 : 2^(s*af)  (kw, 1/8, log2e folded into K/Q)
        uint32_t pa_hi[4][4], pa_lo[4][4];
#pragma unroll
        for (int nf = 0; nf < 8; nf++) {
            int ml = nf*8 + qc2;
            int km0 = s_km[buf*64 + ml], km1 = s_km[buf*64 + ml + 1];
            float p0 = (km0 | pml[nf].x) ? 0.0f : ex2f(sc[nf][0] * pfl[nf].x);
            float p1 = (km1 | pml[nf].y) ? 0.0f : ex2f(sc[nf][1] * pfl[nf].y);
            float p2 = (km0 | pmh[nf].x) ? 0.0f : ex2f(sc[nf][2] * pfh[nf].x);
            float p3 = (km1 | pmh[nf].y) ? 0.0f : ex2f(sc[nf][3] * pfh[nf].y);
            rs_lo += p0 + p1;
            rs_hi += p2 + p3;
            *(float2*)&out_attn[at_lo_row + m0 + ml] = make_float2(p0, p1);
            *(float2*)&out_attn[at_hi_row + m0 + ml] = make_float2(p2, p3);
            __nv_bfloat16 h0,l0,h1,l1,h2,l2,h3,l3;
            split2(p0,h0,l0); split2(p1,h1,l1); split2(p2,h2,l2); split2(p3,h3,l3);
            int ks = nf >> 1, hf = (nf & 1) * 2;
            pa_hi[ks][hf+0] = pk2(h0, h1);
            pa_hi[ks][hf+1] = pk2(h2, h3);
            pa_lo[ks][hf+0] = pk2(l0, l1);
            pa_lo[ks][hf+1] = pk2(l2, l3);
        }

        // AV: hidden += p @ V (3-way split), V from transposed smem
#pragma unroll
        for (int ks = 0; ks < 4; ks++) {
            int mr = ks*16 + qc2;
#pragma unroll
            for (int nf = 0; nf < 8; nf++) {
                int dc = nf*8 + qr;
                uint32_t bhh[2], bll[2];
                bhh[0] = *(const uint32_t*)&Vth[buf][dc][mr];
                bhh[1] = *(const uint32_t*)&Vth[buf][dc][mr+8];
                bll[0] = *(const uint32_t*)&Vtl[buf][dc][mr];
                bll[1] = *(const uint32_t*)&Vtl[buf][dc][mr+8];
                mma_bf16(hid[nf], pa_hi[ks], bhh);
                mma_bf16(hid[nf], pa_hi[ks], bll);
                mma_bf16(hid[nf], pa_lo[ks], bhh);
            }
        }
    }

    // rowsum reduce across the quad, write inverse, write normalized hidden
    rs_lo += __shfl_xor_sync(0xffffffffu, rs_lo, 1);
    rs_lo += __shfl_xor_sync(0xffffffffu, rs_lo, 2);
    rs_hi += __shfl_xor_sync(0xffffffffu, rs_hi, 1);
    rs_hi += __shfl_xor_sync(0xffffffffu, rs_hi, 2);
    float inv_lo = 1.0f / rs_lo;
    float inv_hi = 1.0f / rs_hi;
    if ((lane & 3) == 0) {
        g_inv[(size_t)bh*Nn + n_lo]     = inv_lo;
        g_inv[(size_t)bh*Nn + n_lo + 8] = inv_hi;
    }
#pragma unroll
    for (int nf = 0; nf < 8; nf++) {
        int d = nf*8 + qc2;
        size_t o_lo = ((size_t)b*Nn + n_lo)*Cc + h*64 + d;
        size_t o_hi = o_lo + (size_t)8*Cc;
        *(float2*)&out_hidden[o_lo] = make_float2(hid[nf][0]*inv_lo, hid[nf][1]*inv_lo);
        *(float2*)&out_hidden[o_hi] = make_float2(hid[nf][2]*inv_hi, hid[nf][3]*inv_hi);
    }
}

// ---------------- K3: normalize attn in place ----------------
__global__ __launch_bounds__(256) void norm_kernel(float4* __restrict__ attn4) {
    int i = blockIdx.x * 256 + threadIdx.x;     // 33,554,432 float4s total
    float4 v = attn4[i];
    float inv = g_inv[i >> 9];                  // 512 float4 per (b,h,n) row
    v.x *= inv; v.y *= inv; v.z *= inv; v.w *= inv;
    attn4[i] = v;
}

// ---------------- launch ----------------
extern "C" void kernel_launch(void* const* d_in, const int* in_sizes, int n_in,
                              void* d_out, int out_size) {
    const float* xq    = (const float*)d_in[0];
    const float* xk    = (const float*)d_in[1];
    const float* xv    = (const float*)d_in[2];
    const float* kw    = (const float*)d_in[3];
    const int*   kmask = (const int*)d_in[4];
    const float* af    = (const float*)d_in[5];
    const int*   amask = (const int*)d_in[6];
    const float* Wq    = (const float*)d_in[7];
    const float* bq    = (const float*)d_in[8];
    const float* Wk    = (const float*)d_in[9];
    const float* bk    = (const float*)d_in[10];
    const float* Wv    = (const float*)d_in[11];
    const float* bv    = (const float*)d_in[12];

    float* out_hidden = (float*)d_out;
    float* out_attn   = out_hidden + (size_t)Bb*Nn*Cc;

    const int attn_smem = 4*NSTG*TILE_B + NSTG*64*(int)sizeof(int);   // 74,240 B
    cudaFuncSetAttribute(attn_kernel, cudaFuncAttributeMaxDynamicSharedMemorySize, attn_smem);

    proj_kernel<<<dim3(64, 8, 3), 256>>>(xq, xk, xv, Wq, bq, Wk, bk, Wv, bv, kw);
    attn_kernel<<<dim3(8, 32, 4), 128, attn_smem>>>(kmask, af, amask, out_hidden, out_attn);
    norm_kernel<<<131072, 256>>>((float4*)out_attn);
}

// round 13
// speedup vs baseline: 2.1112x; 1.0491x over previous
#include <cuda_runtime.h>
#include <cuda_bf16.h>
#include <stdint.h>

#define Bb 4
#define Nn 2048
#define Mm 2048
#define Cc 512
#define Hh 8
#define DHd 64
#define LOG2E 1.4426950408889634f

// ---------------- static scratch (no allocations allowed) ----------------
__device__ __nv_bfloat16 g_qhi[Bb*Hh*Nn*DHd];   // [bh][n][dh], pre-scaled by 1/8
__device__ __nv_bfloat16 g_qlo[Bb*Hh*Nn*DHd];
__device__ __nv_bfloat16 g_khi[Bb*Hh*Mm*DHd];   // [bh][m][dh], pre-scaled by kw*log2e
__device__ __nv_bfloat16 g_klo[Bb*Hh*Mm*DHd];
__device__ __nv_bfloat16 g_vhi[Bb*Hh*DHd*Mm];   // TRANSPOSED: [bh][dh][m]
__device__ __nv_bfloat16 g_vlo[Bb*Hh*DHd*Mm];
__device__ float        g_inv[Bb*Hh*Nn];        // 1/rowsum

// ---------------- helpers ----------------
__device__ __forceinline__ void mma_bf16(float c[4], const uint32_t a[4], const uint32_t b[2]) {
    asm volatile(
        "mma.sync.aligned.m16n8k16.row.col.f32.bf16.bf16.f32 "
        "{%0,%1,%2,%3}, {%4,%5,%6,%7}, {%8,%9}, {%0,%1,%2,%3};\n"
        : "+f"(c[0]), "+f"(c[1]), "+f"(c[2]), "+f"(c[3])
        : "r"(a[0]), "r"(a[1]), "r"(a[2]), "r"(a[3]), "r"(b[0]), "r"(b[1]));
}

__device__ __forceinline__ void split2(float x, __nv_bfloat16 &hi, __nv_bfloat16 &lo) {
    hi = __float2bfloat16_rn(x);
    lo = __float2bfloat16_rn(x - __bfloat162float(hi));
}

__device__ __forceinline__ uint32_t pk2(__nv_bfloat16 a, __nv_bfloat16 b) {
    return (uint32_t)__bfloat16_as_ushort(a) | ((uint32_t)__bfloat16_as_ushort(b) << 16);
}

// guaranteed MUFU.EX2
__device__ __forceinline__ float ex2f(float x) {
    float r;
    asm("ex2.approx.ftz.f32 %0, %1;" : "=f"(r) : "f"(x));
    return r;
}

// 16B async copy gmem -> smem (LDGSTS)
__device__ __forceinline__ void cpa16(void* smem, const void* gmem) {
    uint32_t s = (uint32_t)__cvta_generic_to_shared(smem);
    asm volatile("cp.async.cg.shared.global [%0], [%1], 16;" :: "r"(s), "l"(gmem));
}

// ---------------- K1: fused projections (X@W + b), bf16-split mma ----------------
// grid: (64, 8, 3)  block: 256
__global__ __launch_bounds__(256) void proj_kernel(
    const float* __restrict__ xq, const float* __restrict__ xk, const float* __restrict__ xv,
    const float* __restrict__ Wq, const float* __restrict__ bq,
    const float* __restrict__ Wk, const float* __restrict__ bk,
    const float* __restrict__ Wv, const float* __restrict__ bv,
    const float* __restrict__ kw)
{
    const float* X; const float* W; const float* bias;
    __nv_bfloat16 *Ohi, *Olo;
    int z = blockIdx.z;
    if (z == 0)      { X = xq; W = Wq; bias = bq; Ohi = g_qhi; Olo = g_qlo; }
    else if (z == 1) { X = xk; W = Wk; bias = bk; Ohi = g_khi; Olo = g_klo; }
    else             { X = xv; W = Wv; bias = bv; Ohi = g_vhi; Olo = g_vlo; }

    __shared__ __nv_bfloat16 Ahi[128][40], Alo[128][40];   // [row][k], k-chunk 32, pad 8
    __shared__ __nv_bfloat16 Bshi[64][40], Bslo[64][40];   // [col][k] transposed

    int tid = threadIdx.x, lane = tid & 31, warp = tid >> 5;
    int row0 = blockIdx.x * 128;
    int col0 = blockIdx.y * 64;
    int wr = (warp >> 1) * 32, wc = (warp & 1) * 32;
    int qr = lane >> 2, qc2 = (lane & 3) * 2;

    float acc[2][4][4];
#pragma unroll
    for (int m = 0; m < 2; m++)
#pragma unroll
        for (int n = 0; n < 4; n++)
#pragma unroll
            for (int e = 0; e < 4; e++) acc[m][n][e] = 0.0f;

    for (int kc = 0; kc < Cc; kc += 32) {
#pragma unroll
        for (int i = tid; i < 128*8; i += 256) {
            int r = i >> 3, c4 = (i & 7) * 4;
            float4 v = *(const float4*)&X[(size_t)(row0 + r)*Cc + kc + c4];
            __nv_bfloat16 h0,l0,h1,l1,h2,l2,h3,l3;
            split2(v.x, h0, l0); split2(v.y, h1, l1);
            split2(v.z, h2, l2); split2(v.w, h3, l3);
            uint2 th; th.x = pk2(h0,h1); th.y = pk2(h2,h3);
            uint2 tl; tl.x = pk2(l0,l1); tl.y = pk2(l2,l3);
            *(uint2*)&Ahi[r][c4] = th;
            *(uint2*)&Alo[r][c4] = tl;
        }
#pragma unroll
        for (int it = 0; it < 2; it++) {
            int slot = tid + it*256;
            int col = slot & 63, kk0 = (slot >> 6) * 4;
            __nv_bfloat16 h0,l0,h1,l1,h2,l2,h3,l3;
            float v0 = W[(size_t)(kc+kk0+0)*Cc + col0 + col];
            float v1 = W[(size_t)(kc+kk0+1)*Cc + col0 + col];
            float v2 = W[(size_t)(kc+kk0+2)*Cc + col0 + col];
            float v3 = W[(size_t)(kc+kk0+3)*Cc + col0 + col];
            split2(v0, h0, l0); split2(v1, h1, l1);
            split2(v2, h2, l2); split2(v3, h3, l3);
            uint2 th; th.x = pk2(h0,h1); th.y = pk2(h2,h3);
            uint2 tl; tl.x = pk2(l0,l1); tl.y = pk2(l2,l3);
            *(uint2*)&Bshi[col][kk0] = th;
            *(uint2*)&Bslo[col][kk0] = tl;
        }
        __syncthreads();
#pragma unroll
        for (int ks = 0; ks < 2; ks++) {
            int kb = ks*16 + qc2;
            uint32_t a_hi[2][4], a_lo[2][4];
#pragma unroll
            for (int m = 0; m < 2; m++) {
                int r = wr + m*16 + qr;
                a_hi[m][0] = *(const uint32_t*)&Ahi[r][kb];
                a_hi[m][1] = *(const uint32_t*)&Ahi[r+8][kb];
                a_hi[m][2] = *(const uint32_t*)&Ahi[r][kb+8];
                a_hi[m][3] = *(const uint32_t*)&Ahi[r+8][kb+8];
                a_lo[m][0] = *(const uint32_t*)&Alo[r][kb];
                a_lo[m][1] = *(const uint32_t*)&Alo[r+8][kb];
                a_lo[m][2] = *(const uint32_t*)&Alo[r][kb+8];
                a_lo[m][3] = *(const uint32_t*)&Alo[r+8][kb+8];
            }
#pragma unroll
            for (int nf = 0; nf < 4; nf++) {
                int cn = wc + nf*8 + qr;
                uint32_t b_hi[2], b_lo[2];
                b_hi[0] = *(const uint32_t*)&Bshi[cn][kb];
                b_hi[1] = *(const uint32_t*)&Bshi[cn][kb+8];
                b_lo[0] = *(const uint32_t*)&Bslo[cn][kb];
                b_lo[1] = *(const uint32_t*)&Bslo[cn][kb+8];
#pragma unroll
                for (int m = 0; m < 2; m++) {
                    mma_bf16(acc[m][nf], a_hi[m], b_hi);
                    mma_bf16(acc[m][nf], a_hi[m], b_lo);
                    mma_bf16(acc[m][nf], a_lo[m], b_hi);
                }
            }
        }
        __syncthreads();
    }

    int h = blockIdx.y;
#pragma unroll
    for (int m = 0; m < 2; m++) {
#pragma unroll
        for (int e = 0; e < 2; e++) {
            int rg = row0 + wr + m*16 + qr + e*8;
            int bb = rg >> 11, sq = rg & 2047;
            float rsc;
            if (z == 0)      rsc = 0.125f;
            else if (z == 1) rsc = kw[bb*Mm + sq] * LOG2E;
            else             rsc = 1.0f;
#pragma unroll
            for (int nf = 0; nf < 4; nf++) {
                int d = wc + nf*8 + qc2;
                float v0 = (acc[m][nf][e*2+0] + bias[col0+d])   * rsc;
                float v1 = (acc[m][nf][e*2+1] + bias[col0+d+1]) * rsc;
                __nv_bfloat16 h0, l0, h1, l1;
                split2(v0, h0, l0); split2(v1, h1, l1);
                if (z != 2) {
                    size_t o = ((size_t)((bb*Hh + h)*2048 + sq))*64 + d;
                    __nv_bfloat162 th; th.x = h0; th.y = h1;
                    __nv_bfloat162 tl; tl.x = l0; tl.y = l1;
                    *(__nv_bfloat162*)&Ohi[o] = th;
                    *(__nv_bfloat162*)&Olo[o] = tl;
                } else {
                    size_t o = ((size_t)((bb*Hh + h)*64 + d))*2048 + sq;
                    Ohi[o] = h0; Ohi[o + 2048] = h1;
                    Olo[o] = l0; Olo[o + 2048] = l1;
                }
            }
        }
    }
}

// ---------------- K2: fused attention, 128-thread CTAs, 3 CTAs/SM ------
// grid: (h 8, n-blocks 32, b 4) = 1024 CTAs, block 128 (4 warps x 16 rows = 64 q rows).
// Head fastest in grid -> af/amask L2-shared across the 8 CTAs of a (b,nblk).
// 2-stage cp.async pipeline; stage(c+1) issued after the top barrier.
// launch_bounds(128,3): cap regs at 170 so 3 CTAs co-reside (smem 3x74240 fits 228K).
#define TILE_B (64*72*2)        // one [64][72] bf16 buffer = 9216 B
#define NSTG 2
__global__ __launch_bounds__(128, 3) void attn_kernel(
    const int* __restrict__ kmask, const float* __restrict__ af,
    const int* __restrict__ amask,
    float* __restrict__ out_hidden, float* __restrict__ out_attn)
{
    extern __shared__ char dsm[];
    __nv_bfloat16 (*Kh)[64][72]  = (__nv_bfloat16(*)[64][72])(dsm);
    __nv_bfloat16 (*Kl)[64][72]  = (__nv_bfloat16(*)[64][72])(dsm + NSTG*TILE_B);
    __nv_bfloat16 (*Vth)[64][72] = (__nv_bfloat16(*)[64][72])(dsm + 2*NSTG*TILE_B);
    __nv_bfloat16 (*Vtl)[64][72] = (__nv_bfloat16(*)[64][72])(dsm + 3*NSTG*TILE_B);
    int* s_km = (int*)(dsm + 4*NSTG*TILE_B);      // [NSTG][64]

    int tid = threadIdx.x, lane = tid & 31, warp = tid >> 5;
    int qr = lane >> 2, qc2 = (lane & 3) * 2;
    int h = blockIdx.x, b = blockIdx.z;
    int bh = b*Hh + h;
    int n0 = blockIdx.y * 64;
    int wrow = warp * 16;
    int n_lo = n0 + wrow + qr;

    const __nv_bfloat16* khp = g_khi + (size_t)bh*Mm*64;
    const __nv_bfloat16* klp = g_klo + (size_t)bh*Mm*64;
    const __nv_bfloat16* vhp = g_vhi + (size_t)bh*64*Mm;
    const __nv_bfloat16* vlp = g_vlo + (size_t)bh*64*Mm;

    // preload Q fragments (hi/lo) for this warp's 16 rows, all 64 dh
    uint32_t q_hi[4][4], q_lo[4][4];
    {
        const __nv_bfloat16* qh = g_qhi + ((size_t)bh*Nn + n_lo)*64;
        const __nv_bfloat16* ql = g_qlo + ((size_t)bh*Nn + n_lo)*64;
#pragma unroll
        for (int ks = 0; ks < 4; ks++) {
            int kb = ks*16 + qc2;
            q_hi[ks][0] = *(const uint32_t*)&qh[kb];
            q_hi[ks][1] = *(const uint32_t*)&qh[8*64 + kb];
            q_hi[ks][2] = *(const uint32_t*)&qh[kb + 8];
            q_hi[ks][3] = *(const uint32_t*)&qh[8*64 + kb + 8];
            q_lo[ks][0] = *(const uint32_t*)&ql[kb];
            q_lo[ks][1] = *(const uint32_t*)&ql[8*64 + kb];
            q_lo[ks][2] = *(const uint32_t*)&ql[kb + 8];
            q_lo[ks][3] = *(const uint32_t*)&ql[8*64 + kb + 8];
        }
    }

    float hid[8][4];
#pragma unroll
    for (int nf = 0; nf < 8; nf++)
#pragma unroll
        for (int e = 0; e < 4; e++) hid[nf][e] = 0.0f;
    float rs_lo = 0.0f, rs_hi = 0.0f;

    size_t af_lo_row = ((size_t)b*Nn + n_lo)*Mm;
    size_t af_hi_row = af_lo_row + (size_t)8*Mm;
    size_t at_lo_row = ((size_t)bh*Nn + n_lo)*Mm;
    size_t at_hi_row = at_lo_row + (size_t)8*Mm;

    // ---- async stage of one 64-m chunk into buffer `buf` ----
    auto stage = [&](int buf, int m0) {
#pragma unroll
        for (int i = tid; i < 512; i += 128) {
            int r = i >> 3, c8 = (i & 7) * 8;
            cpa16(&Kh[buf][r][c8],  khp + (size_t)(m0 + r)*64 + c8);
            cpa16(&Kl[buf][r][c8],  klp + (size_t)(m0 + r)*64 + c8);
            cpa16(&Vth[buf][r][c8], vhp + (size_t)r*Mm + m0 + c8);
            cpa16(&Vtl[buf][r][c8], vlp + (size_t)r*Mm + m0 + c8);
        }
        if (tid < 16) cpa16(&s_km[buf*64 + tid*4], kmask + b*Mm + m0 + tid*4);
        asm volatile("cp.async.commit_group;" ::: "memory");
    };

    stage(0, 0);

#pragma unroll 1
    for (int c = 0; c < 32; c++) {
        int buf = c & 1;
        int m0 = c * 64;
        asm volatile("cp.async.wait_group 0;" ::: "memory");   // stage(c) done
        __syncthreads();   // all warps finished reading buf (c+1)&1 at iter c-1
        if (c + 1 < 32) stage(buf ^ 1, m0 + 64);

        // QK^T: s (16 x 64) fp32, 3-way bf16 split
        float sc[8][4];
#pragma unroll
        for (int nf = 0; nf < 8; nf++)
#pragma unroll
            for (int e = 0; e < 4; e++) sc[nf][e] = 0.0f;
#pragma unroll
        for (int ks = 0; ks < 4; ks++) {
            int kb = ks*16 + qc2;
#pragma unroll
            for (int nf = 0; nf < 8; nf++) {
                int mc = nf*8 + qr;
                uint32_t bhh[2], bll[2];
                bhh[0] = *(const uint32_t*)&Kh[buf][mc][kb];
                bhh[1] = *(const uint32_t*)&Kh[buf][mc][kb+8];
                bll[0] = *(const uint32_t*)&Kl[buf][mc][kb];
                bll[1] = *(const uint32_t*)&Kl[buf][mc][kb+8];
                mma_bf16(sc[nf], q_hi[ks], bhh);
                mma_bf16(sc[nf], q_hi[ks], bll);
                mma_bf16(sc[nf], q_lo[ks], bhh);
            }
        }

        // epilogue: p = mask ? 0 : 2^(s*af)  (kw, 1/8, log2e folded into K/Q)
        uint32_t pa_hi[4][4], pa_lo[4][4];
#pragma unroll
        for (int nf = 0; nf < 8; nf++) {
            int ml = nf*8 + qc2;
            float2 afl = *(const float2*)&af[af_lo_row + m0 + ml];
            float2 afh = *(const float2*)&af[af_hi_row + m0 + ml];
            int2 aml = *(const int2*)&amask[af_lo_row + m0 + ml];
            int2 amh = *(const int2*)&amask[af_hi_row + m0 + ml];
            int km0 = s_km[buf*64 + ml], km1 = s_km[buf*64 + ml + 1];
            float p0 = (km0 | aml.x) ? 0.0f : ex2f(sc[nf][0] * afl.x);
            float p1 = (km1 | aml.y) ? 0.0f : ex2f(sc[nf][1] * afl.y);
            float p2 = (km0 | amh.x) ? 0.0f : ex2f(sc[nf][2] * afh.x);
            float p3 = (km1 | amh.y) ? 0.0f : ex2f(sc[nf][3] * afh.y);
            rs_lo += p0 + p1;
            rs_hi += p2 + p3;
            *(float2*)&out_attn[at_lo_row + m0 + ml] = make_float2(p0, p1);
            *(float2*)&out_attn[at_hi_row + m0 + ml] = make_float2(p2, p3);
            __nv_bfloat16 h0,l0,h1,l1,h2,l2,h3,l3;
            split2(p0,h0,l0); split2(p1,h1,l1); split2(p2,h2,l2); split2(p3,h3,l3);
            int ks = nf >> 1, hf = (nf & 1) * 2;
            pa_hi[ks][hf+0] = pk2(h0, h1);
            pa_hi[ks][hf+1] = pk2(h2, h3);
            pa_lo[ks][hf+0] = pk2(l0, l1);
            pa_lo[ks][hf+1] = pk2(l2, l3);
        }

        // AV: hidden += p @ V (3-way split), V from transposed smem
#pragma unroll
        for (int ks = 0; ks < 4; ks++) {
            int mr = ks*16 + qc2;
#pragma unroll
            for (int nf = 0; nf < 8; nf++) {
                int dc = nf*8 + qr;
                uint32_t bhh[2], bll[2];
                bhh[0] = *(const uint32_t*)&Vth[buf][dc][mr];
                bhh[1] = *(const uint32_t*)&Vth[buf][dc][mr+8];
                bll[0] = *(const uint32_t*)&Vtl[buf][dc][mr];
                bll[1] = *(const uint32_t*)&Vtl[buf][dc][mr+8];
                mma_bf16(hid[nf], pa_hi[ks], bhh);
                mma_bf16(hid[nf], pa_hi[ks], bll);
                mma_bf16(hid[nf], pa_lo[ks], bhh);
            }
        }
    }

    // rowsum reduce across the quad, write inverse, write normalized hidden
    rs_lo += __shfl_xor_sync(0xffffffffu, rs_lo, 1);
    rs_lo += __shfl_xor_sync(0xffffffffu, rs_lo, 2);
    rs_hi += __shfl_xor_sync(0xffffffffu, rs_hi, 1);
    rs_hi += __shfl_xor_sync(0xffffffffu, rs_hi, 2);
    float inv_lo = 1.0f / rs_lo;
    float inv_hi = 1.0f / rs_hi;
    if ((lane & 3) == 0) {
        g_inv[(size_t)bh*Nn + n_lo]     = inv_lo;
        g_inv[(size_t)bh*Nn + n_lo + 8] = inv_hi;
    }
#pragma unroll
    for (int nf = 0; nf < 8; nf++) {
        int d = nf*8 + qc2;
        size_t o_lo = ((size_t)b*Nn + n_lo)*Cc + h*64 + d;
        size_t o_hi = o_lo + (size_t)8*Cc;
        *(float2*)&out_hidden[o_lo] = make_float2(hid[nf][0]*inv_lo, hid[nf][1]*inv_lo);
        *(float2*)&out_hidden[o_hi] = make_float2(hid[nf][2]*inv_hi, hid[nf][3]*inv_hi);
    }
}

// ---------------- K3: normalize attn in place (MLP=4) ----------------
// grid: 32768 x 256; each thread scales 4 strided float4s.
__global__ __launch_bounds__(256) void norm_kernel(float4* __restrict__ attn4) {
    int base = blockIdx.x * 1024 + threadIdx.x;
    float4 v0 = attn4[base];
    float4 v1 = attn4[base + 256];
    float4 v2 = attn4[base + 512];
    float4 v3 = attn4[base + 768];
    float i0 = g_inv[(base)       >> 9];
    float i1 = g_inv[(base + 256) >> 9];
    float i2 = g_inv[(base + 512) >> 9];
    float i3 = g_inv[(base + 768) >> 9];
    v0.x *= i0; v0.y *= i0; v0.z *= i0; v0.w *= i0;
    v1.x *= i1; v1.y *= i1; v1.z *= i1; v1.w *= i1;
    v2.x *= i2; v2.y *= i2; v2.z *= i2; v2.w *= i2;
    v3.x *= i3; v3.y *= i3; v3.z *= i3; v3.w *= i3;
    attn4[base]       = v0;
    attn4[base + 256] = v1;
    attn4[base + 512] = v2;
    attn4[base + 768] = v3;
}

// ---------------- launch ----------------
extern "C" void kernel_launch(void* const* d_in, const int* in_sizes, int n_in,
                              void* d_out, int out_size) {
    const float* xq    = (const float*)d_in[0];
    const float* xk    = (const float*)d_in[1];
    const float* xv    = (const float*)d_in[2];
    const float* kw    = (const float*)d_in[3];
    const int*   kmask = (const int*)d_in[4];
    const float* af    = (const float*)d_in[5];
    const int*   amask = (const int*)d_in[6];
    const float* Wq    = (const float*)d_in[7];
    const float* bq    = (const float*)d_in[8];
    const float* Wk    = (const float*)d_in[9];
    const float* bk    = (const float*)d_in[10];
    const float* Wv    = (const float*)d_in[11];
    const float* bv    = (const float*)d_in[12];

    float* out_hidden = (float*)d_out;
    float* out_attn   = out_hidden + (size_t)Bb*Nn*Cc;

    const int attn_smem = 4*NSTG*TILE_B + NSTG*64*(int)sizeof(int);   // 74,240 B
    cudaFuncSetAttribute(attn_kernel, cudaFuncAttributeMaxDynamicSharedMemorySize, attn_smem);

    proj_kernel<<<dim3(64, 8, 3), 256>>>(xq, xk, xv, Wq, bq, Wk, bk, Wv, bv, kw);
    attn_kernel<<<dim3(8, 32, 4), 128, attn_smem>>>(kmask, af, amask, out_hidden, out_attn);
    norm_kernel<<<32768, 256>>>((float4*)out_attn);
}

// round 14
// speedup vs baseline: 2.1479x; 1.0174x over previous
#include <cuda_runtime.h>
#include <cuda_bf16.h>
#include <stdint.h>

#define Bb 4
#define Nn 2048
#define Mm 2048
#define Cc 512
#define Hh 8
#define DHd 64
#define LOG2E 1.4426950408889634f

// ---------------- static scratch (no allocations allowed) ----------------
__device__ __nv_bfloat16 g_qhi[Bb*Hh*Nn*DHd];   // [bh][n][dh], pre-scaled by 1/8
__device__ __nv_bfloat16 g_qlo[Bb*Hh*Nn*DHd];
__device__ __nv_bfloat16 g_khi[Bb*Hh*Mm*DHd];   // [bh][m][dh], pre-scaled by kw*log2e
__device__ __nv_bfloat16 g_klo[Bb*Hh*Mm*DHd];
__device__ __nv_bfloat16 g_vhi[Bb*Hh*DHd*Mm];   // TRANSPOSED: [bh][dh][m]
__device__ __nv_bfloat16 g_vlo[Bb*Hh*DHd*Mm];
__device__ float        g_inv[Bb*Hh*Nn];        // 1/rowsum

// ---------------- helpers ----------------
__device__ __forceinline__ void mma_bf16(float c[4], const uint32_t a[4], const uint32_t b[2]) {
    asm volatile(
        "mma.sync.aligned.m16n8k16.row.col.f32.bf16.bf16.f32 "
        "{%0,%1,%2,%3}, {%4,%5,%6,%7}, {%8,%9}, {%0,%1,%2,%3};\n"
        : "+f"(c[0]), "+f"(c[1]), "+f"(c[2]), "+f"(c[3])
        : "r"(a[0]), "r"(a[1]), "r"(a[2]), "r"(a[3]), "r"(b[0]), "r"(b[1]));
}

__device__ __forceinline__ void split2(float x, __nv_bfloat16 &hi, __nv_bfloat16 &lo) {
    hi = __float2bfloat16_rn(x);
    lo = __float2bfloat16_rn(x - __bfloat162float(hi));
}

__device__ __forceinline__ uint32_t pk2(__nv_bfloat16 a, __nv_bfloat16 b) {
    return (uint32_t)__bfloat16_as_ushort(a) | ((uint32_t)__bfloat16_as_ushort(b) << 16);
}

// guaranteed MUFU.EX2
__device__ __forceinline__ float ex2f(float x) {
    float r;
    asm("ex2.approx.ftz.f32 %0, %1;" : "=f"(r) : "f"(x));
    return r;
}

// 16B async copy gmem -> smem (LDGSTS)
__device__ __forceinline__ void cpa16(void* smem, const void* gmem) {
    uint32_t s = (uint32_t)__cvta_generic_to_shared(smem);
    asm volatile("cp.async.cg.shared.global [%0], [%1], 16;" :: "r"(s), "l"(gmem));
}

// ---------------- K1: fused projections (X@W + b), bf16-split mma ----------------
// grid: (64, 8, 3)  block: 256
__global__ __launch_bounds__(256) void proj_kernel(
    const float* __restrict__ xq, const float* __restrict__ xk, const float* __restrict__ xv,
    const float* __restrict__ Wq, const float* __restrict__ bq,
    const float* __restrict__ Wk, const float* __restrict__ bk,
    const float* __restrict__ Wv, const float* __restrict__ bv,
    const float* __restrict__ kw)
{
    const float* X; const float* W; const float* bias;
    __nv_bfloat16 *Ohi, *Olo;
    int z = blockIdx.z;
    if (z == 0)      { X = xq; W = Wq; bias = bq; Ohi = g_qhi; Olo = g_qlo; }
    else if (z == 1) { X = xk; W = Wk; bias = bk; Ohi = g_khi; Olo = g_klo; }
    else             { X = xv; W = Wv; bias = bv; Ohi = g_vhi; Olo = g_vlo; }

    __shared__ __nv_bfloat16 Ahi[128][40], Alo[128][40];   // [row][k], k-chunk 32, pad 8
    __shared__ __nv_bfloat16 Bshi[64][40], Bslo[64][40];   // [col][k] transposed

    int tid = threadIdx.x, lane = tid & 31, warp = tid >> 5;
    int row0 = blockIdx.x * 128;
    int col0 = blockIdx.y * 64;
    int wr = (warp >> 1) * 32, wc = (warp & 1) * 32;
    int qr = lane >> 2, qc2 = (lane & 3) * 2;

    float acc[2][4][4];
#pragma unroll
    for (int m = 0; m < 2; m++)
#pragma unroll
        for (int n = 0; n < 4; n++)
#pragma unroll
            for (int e = 0; e < 4; e++) acc[m][n][e] = 0.0f;

    for (int kc = 0; kc < Cc; kc += 32) {
#pragma unroll
        for (int i = tid; i < 128*8; i += 256) {
            int r = i >> 3, c4 = (i & 7) * 4;
            float4 v = *(const float4*)&X[(size_t)(row0 + r)*Cc + kc + c4];
            __nv_bfloat16 h0,l0,h1,l1,h2,l2,h3,l3;
            split2(v.x, h0, l0); split2(v.y, h1, l1);
            split2(v.z, h2, l2); split2(v.w, h3, l3);
            uint2 th; th.x = pk2(h0,h1); th.y = pk2(h2,h3);
            uint2 tl; tl.x = pk2(l0,l1); tl.y = pk2(l2,l3);
            *(uint2*)&Ahi[r][c4] = th;
            *(uint2*)&Alo[r][c4] = tl;
        }
#pragma unroll
        for (int it = 0; it < 2; it++) {
            int slot = tid + it*256;
            int col = slot & 63, kk0 = (slot >> 6) * 4;
            __nv_bfloat16 h0,l0,h1,l1,h2,l2,h3,l3;
            float v0 = W[(size_t)(kc+kk0+0)*Cc + col0 + col];
            float v1 = W[(size_t)(kc+kk0+1)*Cc + col0 + col];
            float v2 = W[(size_t)(kc+kk0+2)*Cc + col0 + col];
            float v3 = W[(size_t)(kc+kk0+3)*Cc + col0 + col];
            split2(v0, h0, l0); split2(v1, h1, l1);
            split2(v2, h2, l2); split2(v3, h3, l3);
            uint2 th; th.x = pk2(h0,h1); th.y = pk2(h2,h3);
            uint2 tl; tl.x = pk2(l0,l1); tl.y = pk2(l2,l3);
            *(uint2*)&Bshi[col][kk0] = th;
            *(uint2*)&Bslo[col][kk0] = tl;
        }
        __syncthreads();
#pragma unroll
        for (int ks = 0; ks < 2; ks++) {
            int kb = ks*16 + qc2;
            uint32_t a_hi[2][4], a_lo[2][4];
#pragma unroll
            for (int m = 0; m < 2; m++) {
                int r = wr + m*16 + qr;
                a_hi[m][0] = *(const uint32_t*)&Ahi[r][kb];
                a_hi[m][1] = *(const uint32_t*)&Ahi[r+8][kb];
                a_hi[m][2] = *(const uint32_t*)&Ahi[r][kb+8];
                a_hi[m][3] = *(const uint32_t*)&Ahi[r+8][kb+8];
                a_lo[m][0] = *(const uint32_t*)&Alo[r][kb];
                a_lo[m][1] = *(const uint32_t*)&Alo[r+8][kb];
                a_lo[m][2] = *(const uint32_t*)&Alo[r][kb+8];
                a_lo[m][3] = *(const uint32_t*)&Alo[r+8][kb+8];
            }
#pragma unroll
            for (int nf = 0; nf < 4; nf++) {
                int cn = wc + nf*8 + qr;
                uint32_t b_hi[2], b_lo[2];
                b_hi[0] = *(const uint32_t*)&Bshi[cn][kb];
                b_hi[1] = *(const uint32_t*)&Bshi[cn][kb+8];
                b_lo[0] = *(const uint32_t*)&Bslo[cn][kb];
                b_lo[1] = *(const uint32_t*)&Bslo[cn][kb+8];
#pragma unroll
                for (int m = 0; m < 2; m++) {
                    mma_bf16(acc[m][nf], a_hi[m], b_hi);
                    mma_bf16(acc[m][nf], a_hi[m], b_lo);
                    mma_bf16(acc[m][nf], a_lo[m], b_hi);
                }
            }
        }
        __syncthreads();
    }

    int h = blockIdx.y;
#pragma unroll
    for (int m = 0; m < 2; m++) {
#pragma unroll
        for (int e = 0; e < 2; e++) {
            int rg = row0 + wr + m*16 + qr + e*8;
            int bb = rg >> 11, sq = rg & 2047;
            float rsc;
            if (z == 0)      rsc = 0.125f;
            else if (z == 1) rsc = kw[bb*Mm + sq] * LOG2E;
            else             rsc = 1.0f;
#pragma unroll
            for (int nf = 0; nf < 4; nf++) {
                int d = wc + nf*8 + qc2;
                float v0 = (acc[m][nf][e*2+0] + bias[col0+d])   * rsc;
                float v1 = (acc[m][nf][e*2+1] + bias[col0+d+1]) * rsc;
                __nv_bfloat16 h0, l0, h1, l1;
                split2(v0, h0, l0); split2(v1, h1, l1);
                if (z != 2) {
                    size_t o = ((size_t)((bb*Hh + h)*2048 + sq))*64 + d;
                    __nv_bfloat162 th; th.x = h0; th.y = h1;
                    __nv_bfloat162 tl; tl.x = l0; tl.y = l1;
                    *(__nv_bfloat162*)&Ohi[o] = th;
                    *(__nv_bfloat162*)&Olo[o] = tl;
                } else {
                    size_t o = ((size_t)((bb*Hh + h)*64 + d))*2048 + sq;
                    Ohi[o] = h0; Ohi[o + 2048] = h1;
                    Olo[o] = l0; Olo[o + 2048] = l1;
                }
            }
        }
    }
}

// ---------------- K2: fused attention, 128-thread CTAs, 3 CTAs/SM ------
// grid: (h 8, n-blocks 32, b 4) = 1024 CTAs, block 128 (4 warps x 16 rows = 64 q rows).
// Each 64-m chunk is processed as TWO 32-m half-chunks (QK->exp->AV per half) to
// halve peak live registers (sc 16, pa 16) so launch_bounds(128,3) is spill-free.
#define TILE_B (64*72*2)        // one [64][72] bf16 buffer = 9216 B
#define NSTG 2
__global__ __launch_bounds__(128, 3) void attn_kernel(
    const int* __restrict__ kmask, const float* __restrict__ af,
    const int* __restrict__ amask,
    float* __restrict__ out_hidden, float* __restrict__ out_attn)
{
    extern __shared__ char dsm[];
    __nv_bfloat16 (*Kh)[64][72]  = (__nv_bfloat16(*)[64][72])(dsm);
    __nv_bfloat16 (*Kl)[64][72]  = (__nv_bfloat16(*)[64][72])(dsm + NSTG*TILE_B);
    __nv_bfloat16 (*Vth)[64][72] = (__nv_bfloat16(*)[64][72])(dsm + 2*NSTG*TILE_B);
    __nv_bfloat16 (*Vtl)[64][72] = (__nv_bfloat16(*)[64][72])(dsm + 3*NSTG*TILE_B);
    int* s_km = (int*)(dsm + 4*NSTG*TILE_B);      // [NSTG][64]

    int tid = threadIdx.x, lane = tid & 31, warp = tid >> 5;
    int qr = lane >> 2, qc2 = (lane & 3) * 2;
    int h = blockIdx.x, b = blockIdx.z;
    int bh = b*Hh + h;
    int n0 = blockIdx.y * 64;
    int wrow = warp * 16;
    int n_lo = n0 + wrow + qr;

    const __nv_bfloat16* khp = g_khi + (size_t)bh*Mm*64;
    const __nv_bfloat16* klp = g_klo + (size_t)bh*Mm*64;
    const __nv_bfloat16* vhp = g_vhi + (size_t)bh*64*Mm;
    const __nv_bfloat16* vlp = g_vlo + (size_t)bh*64*Mm;

    // preload Q fragments (hi/lo) for this warp's 16 rows, all 64 dh
    uint32_t q_hi[4][4], q_lo[4][4];
    {
        const __nv_bfloat16* qh = g_qhi + ((size_t)bh*Nn + n_lo)*64;
        const __nv_bfloat16* ql = g_qlo + ((size_t)bh*Nn + n_lo)*64;
#pragma unroll
        for (int ks = 0; ks < 4; ks++) {
            int kb = ks*16 + qc2;
            q_hi[ks][0] = *(const uint32_t*)&qh[kb];
            q_hi[ks][1] = *(const uint32_t*)&qh[8*64 + kb];
            q_hi[ks][2] = *(const uint32_t*)&qh[kb + 8];
            q_hi[ks][3] = *(const uint32_t*)&qh[8*64 + kb + 8];
            q_lo[ks][0] = *(const uint32_t*)&ql[kb];
            q_lo[ks][1] = *(const uint32_t*)&ql[8*64 + kb];
            q_lo[ks][2] = *(const uint32_t*)&ql[kb + 8];
            q_lo[ks][3] = *(const uint32_t*)&ql[8*64 + kb + 8];
        }
    }

    float hid[8][4];
#pragma unroll
    for (int nf = 0; nf < 8; nf++)
#pragma unroll
        for (int e = 0; e < 4; e++) hid[nf][e] = 0.0f;
    float rs_lo = 0.0f, rs_hi = 0.0f;

    size_t af_lo_row = ((size_t)b*Nn + n_lo)*Mm;
    size_t af_hi_row = af_lo_row + (size_t)8*Mm;
    size_t at_lo_row = ((size_t)bh*Nn + n_lo)*Mm;
    size_t at_hi_row = at_lo_row + (size_t)8*Mm;

    // ---- async stage of one 64-m chunk into buffer `buf` ----
    auto stage = [&](int buf, int m0) {
#pragma unroll
        for (int i = tid; i < 512; i += 128) {
            int r = i >> 3, c8 = (i & 7) * 8;
            cpa16(&Kh[buf][r][c8],  khp + (size_t)(m0 + r)*64 + c8);
            cpa16(&Kl[buf][r][c8],  klp + (size_t)(m0 + r)*64 + c8);
            cpa16(&Vth[buf][r][c8], vhp + (size_t)r*Mm + m0 + c8);
            cpa16(&Vtl[buf][r][c8], vlp + (size_t)r*Mm + m0 + c8);
        }
        if (tid < 16) cpa16(&s_km[buf*64 + tid*4], kmask + b*Mm + m0 + tid*4);
        asm volatile("cp.async.commit_group;" ::: "memory");
    };

    stage(0, 0);

#pragma unroll 1
    for (int c = 0; c < 32; c++) {
        int buf = c & 1;
        int m0 = c * 64;
        asm volatile("cp.async.wait_group 0;" ::: "memory");   // stage(c) done
        __syncthreads();   // all warps finished reading buf (c+1)&1 at iter c-1
        if (c + 1 < 32) stage(buf ^ 1, m0 + 64);

#pragma unroll
        for (int half = 0; half < 2; half++) {
            // QK^T for this 32-m half: sc[nfh] covers m cols half*32 + nfh*8 + qr
            float sc[4][4];
#pragma unroll
            for (int nfh = 0; nfh < 4; nfh++)
#pragma unroll
                for (int e = 0; e < 4; e++) sc[nfh][e] = 0.0f;
#pragma unroll
            for (int ks = 0; ks < 4; ks++) {
                int kb = ks*16 + qc2;
#pragma unroll
                for (int nfh = 0; nfh < 4; nfh++) {
                    int mc = half*32 + nfh*8 + qr;
                    uint32_t bhh[2], bll[2];
                    bhh[0] = *(const uint32_t*)&Kh[buf][mc][kb];
                    bhh[1] = *(const uint32_t*)&Kh[buf][mc][kb+8];
                    bll[0] = *(const uint32_t*)&Kl[buf][mc][kb];
                    bll[1] = *(const uint32_t*)&Kl[buf][mc][kb+8];
                    mma_bf16(sc[nfh], q_hi[ks], bhh);
                    mma_bf16(sc[nfh], q_hi[ks], bll);
                    mma_bf16(sc[nfh], q_lo[ks], bhh);
                }
            }

            // epilogue for this half: p = mask ? 0 : 2^(s*af)
            uint32_t pa_hi[2][4], pa_lo[2][4];
#pragma unroll
            for (int nfh = 0; nfh < 4; nfh++) {
                int ml = half*32 + nfh*8 + qc2;
                float2 afl = *(const float2*)&af[af_lo_row + m0 + ml];
                float2 afh = *(const float2*)&af[af_hi_row + m0 + ml];
                int2 aml = *(const int2*)&amask[af_lo_row + m0 + ml];
                int2 amh = *(const int2*)&amask[af_hi_row + m0 + ml];
                int km0 = s_km[buf*64 + ml], km1 = s_km[buf*64 + ml + 1];
                float p0 = (km0 | aml.x) ? 0.0f : ex2f(sc[nfh][0] * afl.x);
                float p1 = (km1 | aml.y) ? 0.0f : ex2f(sc[nfh][1] * afl.y);
                float p2 = (km0 | amh.x) ? 0.0f : ex2f(sc[nfh][2] * afh.x);
                float p3 = (km1 | amh.y) ? 0.0f : ex2f(sc[nfh][3] * afh.y);
                rs_lo += p0 + p1;
                rs_hi += p2 + p3;
                *(float2*)&out_attn[at_lo_row + m0 + ml] = make_float2(p0, p1);
                *(float2*)&out_attn[at_hi_row + m0 + ml] = make_float2(p2, p3);
                __nv_bfloat16 h0,l0,h1,l1,h2,l2,h3,l3;
                split2(p0,h0,l0); split2(p1,h1,l1); split2(p2,h2,l2); split2(p3,h3,l3);
                int ksl = nfh >> 1, hf = (nfh & 1) * 2;
                pa_hi[ksl][hf+0] = pk2(h0, h1);
                pa_hi[ksl][hf+1] = pk2(h2, h3);
                pa_lo[ksl][hf+0] = pk2(l0, l1);
                pa_lo[ksl][hf+1] = pk2(l2, l3);
            }

            // AV for this half: rows half*32..half*32+31 of V^T tile
#pragma unroll
            for (int ksl = 0; ksl < 2; ksl++) {
                int mr = half*32 + ksl*16 + qc2;
#pragma unroll
                for (int nf = 0; nf < 8; nf++) {
                    int dc = nf*8 + qr;
                    uint32_t bhh[2], bll[2];
                    bhh[0] = *(const uint32_t*)&Vth[buf][dc][mr];
                    bhh[1] = *(const uint32_t*)&Vth[buf][dc][mr+8];
                    bll[0] = *(const uint32_t*)&Vtl[buf][dc][mr];
                    bll[1] = *(const uint32_t*)&Vtl[buf][dc][mr+8];
                    mma_bf16(hid[nf], pa_hi[ksl], bhh);
                    mma_bf16(hid[nf], pa_hi[ksl], bll);
                    mma_bf16(hid[nf], pa_lo[ksl], bhh);
                }
            }
        }
    }

    // rowsum reduce across the quad, write inverse, write normalized hidden
    rs_lo += __shfl_xor_sync(0xffffffffu, rs_lo, 1);
    rs_lo += __shfl_xor_sync(0xffffffffu, rs_lo, 2);
    rs_hi += __shfl_xor_sync(0xffffffffu, rs_hi, 1);
    rs_hi += __shfl_xor_sync(0xffffffffu, rs_hi, 2);
    float inv_lo = 1.0f / rs_lo;
    float inv_hi = 1.0f / rs_hi;
    if ((lane & 3) == 0) {
        g_inv[(size_t)bh*Nn + n_lo]     = inv_lo;
        g_inv[(size_t)bh*Nn + n_lo + 8] = inv_hi;
    }
#pragma unroll
    for (int nf = 0; nf < 8; nf++) {
        int d = nf*8 + qc2;
        size_t o_lo = ((size_t)b*Nn + n_lo)*Cc + h*64 + d;
        size_t o_hi = o_lo + (size_t)8*Cc;
        *(float2*)&out_hidden[o_lo] = make_float2(hid[nf][0]*inv_lo, hid[nf][1]*inv_lo);
        *(float2*)&out_hidden[o_hi] = make_float2(hid[nf][2]*inv_hi, hid[nf][3]*inv_hi);
    }
}

// ---------------- K3: normalize attn in place (MLP=4) ----------------
// grid: 32768 x 256; each thread scales 4 strided float4s.
__global__ __launch_bounds__(256) void norm_kernel(float4* __restrict__ attn4) {
    int base = blockIdx.x * 1024 + threadIdx.x;
    float4 v0 = attn4[base];
    float4 v1 = attn4[base + 256];
    float4 v2 = attn4[base + 512];
    float4 v3 = attn4[base + 768];
    float i0 = g_inv[(base)       >> 9];
    float i1 = g_inv[(base + 256) >> 9];
    float i2 = g_inv[(base + 512) >> 9];
    float i3 = g_inv[(base + 768) >> 9];
    v0.x *= i0; v0.y *= i0; v0.z *= i0; v0.w *= i0;
    v1.x *= i1; v1.y *= i1; v1.z *= i1; v1.w *= i1;
    v2.x *= i2; v2.y *= i2; v2.z *= i2; v2.w *= i2;
    v3.x *= i3; v3.y *= i3; v3.z *= i3; v3.w *= i3;
    attn4[base]       = v0;
    attn4[base + 256] = v1;
    attn4[base + 512] = v2;
    attn4[base + 768] = v3;
}

// ---------------- launch ----------------
extern "C" void kernel_launch(void* const* d_in, const int* in_sizes, int n_in,
                              void* d_out, int out_size) {
    const float* xq    = (const float*)d_in[0];
    const float* xk    = (const float*)d_in[1];
    const float* xv    = (const float*)d_in[2];
    const float* kw    = (const float*)d_in[3];
    const int*   kmask = (const int*)d_in[4];
    const float* af    = (const float*)d_in[5];
    const int*   amask = (const int*)d_in[6];
    const float* Wq    = (const float*)d_in[7];
    const float* bq    = (const float*)d_in[8];
    const float* Wk    = (const float*)d_in[9];
    const float* bk    = (const float*)d_in[10];
    const float* Wv    = (const float*)d_in[11];
    const float* bv    = (const float*)d_in[12];

    float* out_hidden = (float*)d_out;
    float* out_attn   = out_hidden + (size_t)Bb*Nn*Cc;

    const int attn_smem = 4*NSTG*TILE_B + NSTG*64*(int)sizeof(int);   // 74,240 B
    cudaFuncSetAttribute(attn_kernel, cudaFuncAttributeMaxDynamicSharedMemorySize, attn_smem);

    proj_kernel<<<dim3(64, 8, 3), 256>>>(xq, xk, xv, Wq, bq, Wk, bk, Wv, bv, kw);
    attn_kernel<<<dim3(8, 32, 4), 128, attn_smem>>>(kmask, af, amask, out_hidden, out_attn);
    norm_kernel<<<32768, 256>>>((float4*)out_attn);
}

// round 15
// speedup vs baseline: 2.3098x; 1.0754x over previous
#include <cuda_runtime.h>
#include <cuda_bf16.h>
#include <cuda_fp16.h>
#include <stdint.h>

#define Bb 4
#define Nn 2048
#define Mm 2048
#define Cc 512
#define Hh 8
#define DHd 64
#define LOG2E 1.4426950408889634f

// ---------------- static scratch (no allocations allowed) ----------------
__device__ __half g_qhi[Bb*Hh*Nn*DHd];   // [bh][n][dh], fp16 hi, pre-scaled by 1/8
__device__ __half g_qlo[Bb*Hh*Nn*DHd];   // fp16 lo
__device__ __half g_k  [Bb*Hh*Mm*DHd];   // [bh][m][dh], SINGLE fp16, pre-scaled kw*log2e
__device__ __half g_vhi[Bb*Hh*DHd*Mm];   // TRANSPOSED [bh][dh][m], fp16 hi
__device__ __half g_vlo[Bb*Hh*DHd*Mm];   // fp16 lo
__device__ float  g_inv[Bb*Hh*Nn];       // 1/rowsum

// ---------------- helpers ----------------
__device__ __forceinline__ void mma_bf16(float c[4], const uint32_t a[4], const uint32_t b[2]) {
    asm volatile(
        "mma.sync.aligned.m16n8k16.row.col.f32.bf16.bf16.f32 "
        "{%0,%1,%2,%3}, {%4,%5,%6,%7}, {%8,%9}, {%0,%1,%2,%3};\n"
        : "+f"(c[0]), "+f"(c[1]), "+f"(c[2]), "+f"(c[3])
        : "r"(a[0]), "r"(a[1]), "r"(a[2]), "r"(a[3]), "r"(b[0]), "r"(b[1]));
}

__device__ __forceinline__ void mma_f16(float c[4], const uint32_t a[4], const uint32_t b[2]) {
    asm volatile(
        "mma.sync.aligned.m16n8k16.row.col.f32.f16.f16.f32 "
        "{%0,%1,%2,%3}, {%4,%5,%6,%7}, {%8,%9}, {%0,%1,%2,%3};\n"
        : "+f"(c[0]), "+f"(c[1]), "+f"(c[2]), "+f"(c[3])
        : "r"(a[0]), "r"(a[1]), "r"(a[2]), "r"(a[3]), "r"(b[0]), "r"(b[1]));
}

__device__ __forceinline__ void split2(float x, __nv_bfloat16 &hi, __nv_bfloat16 &lo) {
    hi = __float2bfloat16_rn(x);
    lo = __float2bfloat16_rn(x - __bfloat162float(hi));
}

__device__ __forceinline__ void split2h(float x, __half &hi, __half &lo) {
    hi = __float2half_rn(x);
    lo = __float2half_rn(x - __half2float(hi));
}

__device__ __forceinline__ uint32_t pk2(__nv_bfloat16 a, __nv_bfloat16 b) {
    return (uint32_t)__bfloat16_as_ushort(a) | ((uint32_t)__bfloat16_as_ushort(b) << 16);
}

__device__ __forceinline__ uint32_t pk2h(__half a, __half b) {
    return (uint32_t)__half_as_ushort(a) | ((uint32_t)__half_as_ushort(b) << 16);
}

// guaranteed MUFU.EX2
__device__ __forceinline__ float ex2f(float x) {
    float r;
    asm("ex2.approx.ftz.f32 %0, %1;" : "=f"(r) : "f"(x));
    return r;
}

// 16B async copy gmem -> smem (LDGSTS)
__device__ __forceinline__ void cpa16(void* smem, const void* gmem) {
    uint32_t s = (uint32_t)__cvta_generic_to_shared(smem);
    asm volatile("cp.async.cg.shared.global [%0], [%1], 16;" :: "r"(s), "l"(gmem));
}

// ---------------- K1: fused projections (X@W + b), bf16-split mma ----------------
// grid: (64, 8, 3)  block: 256.  Internal GEMM unchanged; outputs now fp16-coded.
__global__ __launch_bounds__(256) void proj_kernel(
    const float* __restrict__ xq, const float* __restrict__ xk, const float* __restrict__ xv,
    const float* __restrict__ Wq, const float* __restrict__ bq,
    const float* __restrict__ Wk, const float* __restrict__ bk,
    const float* __restrict__ Wv, const float* __restrict__ bv,
    const float* __restrict__ kw)
{
    const float* X; const float* W; const float* bias;
    int z = blockIdx.z;
    if (z == 0)      { X = xq; W = Wq; bias = bq; }
    else if (z == 1) { X = xk; W = Wk; bias = bk; }
    else             { X = xv; W = Wv; bias = bv; }

    __shared__ __nv_bfloat16 Ahi[128][40], Alo[128][40];   // [row][k], k-chunk 32, pad 8
    __shared__ __nv_bfloat16 Bshi[64][40], Bslo[64][40];   // [col][k] transposed

    int tid = threadIdx.x, lane = tid & 31, warp = tid >> 5;
    int row0 = blockIdx.x * 128;
    int col0 = blockIdx.y * 64;
    int wr = (warp >> 1) * 32, wc = (warp & 1) * 32;
    int qr = lane >> 2, qc2 = (lane & 3) * 2;

    float acc[2][4][4];
#pragma unroll
    for (int m = 0; m < 2; m++)
#pragma unroll
        for (int n = 0; n < 4; n++)
#pragma unroll
            for (int e = 0; e < 4; e++) acc[m][n][e] = 0.0f;

    for (int kc = 0; kc < Cc; kc += 32) {
#pragma unroll
        for (int i = tid; i < 128*8; i += 256) {
            int r = i >> 3, c4 = (i & 7) * 4;
            float4 v = *(const float4*)&X[(size_t)(row0 + r)*Cc + kc + c4];
            __nv_bfloat16 h0,l0,h1,l1,h2,l2,h3,l3;
            split2(v.x, h0, l0); split2(v.y, h1, l1);
            split2(v.z, h2, l2); split2(v.w, h3, l3);
            uint2 th; th.x = pk2(h0,h1); th.y = pk2(h2,h3);
            uint2 tl; tl.x = pk2(l0,l1); tl.y = pk2(l2,l3);
            *(uint2*)&Ahi[r][c4] = th;
            *(uint2*)&Alo[r][c4] = tl;
        }
#pragma unroll
        for (int it = 0; it < 2; it++) {
            int slot = tid + it*256;
            int col = slot & 63, kk0 = (slot >> 6) * 4;
            __nv_bfloat16 h0,l0,h1,l1,h2,l2,h3,l3;
            float v0 = W[(size_t)(kc+kk0+0)*Cc + col0 + col];
            float v1 = W[(size_t)(kc+kk0+1)*Cc + col0 + col];
            float v2 = W[(size_t)(kc+kk0+2)*Cc + col0 + col];
            float v3 = W[(size_t)(kc+kk0+3)*Cc + col0 + col];
            split2(v0, h0, l0); split2(v1, h1, l1);
            split2(v2, h2, l2); split2(v3, h3, l3);
            uint2 th; th.x = pk2(h0,h1); th.y = pk2(h2,h3);
            uint2 tl; tl.x = pk2(l0,l1); tl.y = pk2(l2,l3);
            *(uint2*)&Bshi[col][kk0] = th;
            *(uint2*)&Bslo[col][kk0] = tl;
        }
        __syncthreads();
#pragma unroll
        for (int ks = 0; ks < 2; ks++) {
            int kb = ks*16 + qc2;
            uint32_t a_hi[2][4], a_lo[2][4];
#pragma unroll
            for (int m = 0; m < 2; m++) {
                int r = wr + m*16 + qr;
                a_hi[m][0] = *(const uint32_t*)&Ahi[r][kb];
                a_hi[m][1] = *(const uint32_t*)&Ahi[r+8][kb];
                a_hi[m][2] = *(const uint32_t*)&Ahi[r][kb+8];
                a_hi[m][3] = *(const uint32_t*)&Ahi[r+8][kb+8];
                a_lo[m][0] = *(const uint32_t*)&Alo[r][kb];
                a_lo[m][1] = *(const uint32_t*)&Alo[r+8][kb];
                a_lo[m][2] = *(const uint32_t*)&Alo[r][kb+8];
                a_lo[m][3] = *(const uint32_t*)&Alo[r+8][kb+8];
            }
#pragma unroll
            for (int nf = 0; nf < 4; nf++) {
                int cn = wc + nf*8 + qr;
                uint32_t b_hi[2], b_lo[2];
                b_hi[0] = *(const uint32_t*)&Bshi[cn][kb];
                b_hi[1] = *(const uint32_t*)&Bshi[cn][kb+8];
                b_lo[0] = *(const uint32_t*)&Bslo[cn][kb];
                b_lo[1] = *(const uint32_t*)&Bslo[cn][kb+8];
#pragma unroll
                for (int m = 0; m < 2; m++) {
                    mma_bf16(acc[m][nf], a_hi[m], b_hi);
                    mma_bf16(acc[m][nf], a_hi[m], b_lo);
                    mma_bf16(acc[m][nf], a_lo[m], b_hi);
                }
            }
        }
        __syncthreads();
    }

    int h = blockIdx.y;
#pragma unroll
    for (int m = 0; m < 2; m++) {
#pragma unroll
        for (int e = 0; e < 2; e++) {
            int rg = row0 + wr + m*16 + qr + e*8;
            int bb = rg >> 11, sq = rg & 2047;
            float rsc;
            if (z == 0)      rsc = 0.125f;
            else if (z == 1) rsc = kw[bb*Mm + sq] * LOG2E;
            else             rsc = 1.0f;
#pragma unroll
            for (int nf = 0; nf < 4; nf++) {
                int d = wc + nf*8 + qc2;
                float v0 = (acc[m][nf][e*2+0] + bias[col0+d])   * rsc;
                float v1 = (acc[m][nf][e*2+1] + bias[col0+d+1]) * rsc;
                if (z == 0) {
                    size_t o = ((size_t)((bb*Hh + h)*2048 + sq))*64 + d;
                    __half h0,l0,h1,l1;
                    split2h(v0, h0, l0); split2h(v1, h1, l1);
                    *(uint32_t*)&g_qhi[o] = pk2h(h0, h1);
                    *(uint32_t*)&g_qlo[o] = pk2h(l0, l1);
                } else if (z == 1) {
                    size_t o = ((size_t)((bb*Hh + h)*2048 + sq))*64 + d;
                    *(uint32_t*)&g_k[o] = pk2h(__float2half_rn(v0), __float2half_rn(v1));
                } else {
                    // transposed: [bh][dh][m], fp16 hi/lo
                    size_t o = ((size_t)((bb*Hh + h)*64 + d))*2048 + sq;
                    __half h0,l0,h1,l1;
                    split2h(v0, h0, l0); split2h(v1, h1, l1);
                    g_vhi[o] = h0; g_vhi[o + 2048] = h1;
                    g_vlo[o] = l0; g_vlo[o + 2048] = l1;
                }
            }
        }
    }
}

// ---------------- K2: fused attention, fp16 datapath, 128-thread CTAs ------
// grid: (h 8, n-blocks 32, b 4) = 1024 CTAs, block 128 (4 warps x 16 rows = 64 q rows).
// QK: q fp16 hi/lo x K single fp16 = 2 MMAs.  AV: p single fp16 x V fp16 hi/lo = 2 MMAs.
// out_attn still receives fp32 p (attn output precision preserved).
#define TILE_B (64*72*2)        // one [64][72] fp16 buffer = 9216 B
#define NSTG 2
__global__ __launch_bounds__(128, 3) void attn_kernel(
    const int* __restrict__ kmask, const float* __restrict__ af,
    const int* __restrict__ amask,
    float* __restrict__ out_hidden, float* __restrict__ out_attn)
{
    extern __shared__ char dsm[];
    __half (*Ks)[64][72]  = (__half(*)[64][72])(dsm);
    __half (*Vth)[64][72] = (__half(*)[64][72])(dsm + NSTG*TILE_B);
    __half (*Vtl)[64][72] = (__half(*)[64][72])(dsm + 2*NSTG*TILE_B);
    int* s_km = (int*)(dsm + 3*NSTG*TILE_B);      // [NSTG][64]

    int tid = threadIdx.x, lane = tid & 31, warp = tid >> 5;
    int qr = lane >> 2, qc2 = (lane & 3) * 2;
    int h = blockIdx.x, b = blockIdx.z;
    int bh = b*Hh + h;
    int n0 = blockIdx.y * 64;
    int wrow = warp * 16;
    int n_lo = n0 + wrow + qr;

    const __half* khp = g_k   + (size_t)bh*Mm*64;
    const __half* vhp = g_vhi + (size_t)bh*64*Mm;
    const __half* vlp = g_vlo + (size_t)bh*64*Mm;

    // preload Q fragments (fp16 hi/lo) for this warp's 16 rows, all 64 dh
    uint32_t q_hi[4][4], q_lo[4][4];
    {
        const __half* qh = g_qhi + ((size_t)bh*Nn + n_lo)*64;
        const __half* ql = g_qlo + ((size_t)bh*Nn + n_lo)*64;
#pragma unroll
        for (int ks = 0; ks < 4; ks++) {
            int kb = ks*16 + qc2;
            q_hi[ks][0] = *(const uint32_t*)&qh[kb];
            q_hi[ks][1] = *(const uint32_t*)&qh[8*64 + kb];
            q_hi[ks][2] = *(const uint32_t*)&qh[kb + 8];
            q_hi[ks][3] = *(const uint32_t*)&qh[8*64 + kb + 8];
            q_lo[ks][0] = *(const uint32_t*)&ql[kb];
            q_lo[ks][1] = *(const uint32_t*)&ql[8*64 + kb];
            q_lo[ks][2] = *(const uint32_t*)&ql[kb + 8];
            q_lo[ks][3] = *(const uint32_t*)&ql[8*64 + kb + 8];
        }
    }

    float hid[8][4];
#pragma unroll
    for (int nf = 0; nf < 8; nf++)
#pragma unroll
        for (int e = 0; e < 4; e++) hid[nf][e] = 0.0f;
    float rs_lo = 0.0f, rs_hi = 0.0f;

    size_t af_lo_row = ((size_t)b*Nn + n_lo)*Mm;
    size_t af_hi_row = af_lo_row + (size_t)8*Mm;
    size_t at_lo_row = ((size_t)bh*Nn + n_lo)*Mm;
    size_t at_hi_row = at_lo_row + (size_t)8*Mm;

    // ---- async stage of one 64-m chunk into buffer `buf` ----
    auto stage = [&](int buf, int m0) {
#pragma unroll
        for (int i = tid; i < 512; i += 128) {
            int r = i >> 3, c8 = (i & 7) * 8;
            cpa16(&Ks[buf][r][c8],  khp + (size_t)(m0 + r)*64 + c8);
            cpa16(&Vth[buf][r][c8], vhp + (size_t)r*Mm + m0 + c8);
            cpa16(&Vtl[buf][r][c8], vlp + (size_t)r*Mm + m0 + c8);
        }
        if (tid < 16) cpa16(&s_km[buf*64 + tid*4], kmask + b*Mm + m0 + tid*4);
        asm volatile("cp.async.commit_group;" ::: "memory");
    };

    stage(0, 0);

#pragma unroll 1
    for (int c = 0; c < 32; c++) {
        int buf = c & 1;
        int m0 = c * 64;
        asm volatile("cp.async.wait_group 0;" ::: "memory");   // stage(c) done
        __syncthreads();   // all warps finished reading buf (c+1)&1 at iter c-1
        if (c + 1 < 32) stage(buf ^ 1, m0 + 64);

#pragma unroll
        for (int half = 0; half < 2; half++) {
            // QK^T for this 32-m half: 2 MMAs per fragment (q hi/lo x k single)
            float sc[4][4];
#pragma unroll
            for (int nfh = 0; nfh < 4; nfh++)
#pragma unroll
                for (int e = 0; e < 4; e++) sc[nfh][e] = 0.0f;
#pragma unroll
            for (int ks = 0; ks < 4; ks++) {
                int kb = ks*16 + qc2;
#pragma unroll
                for (int nfh = 0; nfh < 4; nfh++) {
                    int mc = half*32 + nfh*8 + qr;
                    uint32_t bk[2];
                    bk[0] = *(const uint32_t*)&Ks[buf][mc][kb];
                    bk[1] = *(const uint32_t*)&Ks[buf][mc][kb+8];
                    mma_f16(sc[nfh], q_hi[ks], bk);
                    mma_f16(sc[nfh], q_lo[ks], bk);
                }
            }

            // epilogue: p = mask ? 0 : 2^(s*af);  store fp32 p; pack single-fp16 p frags
            uint32_t pa[2][4];
#pragma unroll
            for (int nfh = 0; nfh < 4; nfh++) {
                int ml = half*32 + nfh*8 + qc2;
                float2 afl = *(const float2*)&af[af_lo_row + m0 + ml];
                float2 afh = *(const float2*)&af[af_hi_row + m0 + ml];
                int2 aml = *(const int2*)&amask[af_lo_row + m0 + ml];
                int2 amh = *(const int2*)&amask[af_hi_row + m0 + ml];
                int km0 = s_km[buf*64 + ml], km1 = s_km[buf*64 + ml + 1];
                float p0 = (km0 | aml.x) ? 0.0f : ex2f(sc[nfh][0] * afl.x);
                float p1 = (km1 | aml.y) ? 0.0f : ex2f(sc[nfh][1] * afl.y);
                float p2 = (km0 | amh.x) ? 0.0f : ex2f(sc[nfh][2] * afh.x);
                float p3 = (km1 | amh.y) ? 0.0f : ex2f(sc[nfh][3] * afh.y);
                rs_lo += p0 + p1;
                rs_hi += p2 + p3;
                *(float2*)&out_attn[at_lo_row + m0 + ml] = make_float2(p0, p1);
                *(float2*)&out_attn[at_hi_row + m0 + ml] = make_float2(p2, p3);
                int ksl = nfh >> 1, hf = (nfh & 1) * 2;
                pa[ksl][hf+0] = pk2h(__float2half_rn(p0), __float2half_rn(p1));
                pa[ksl][hf+1] = pk2h(__float2half_rn(p2), __float2half_rn(p3));
            }

            // AV for this half: 2 MMAs per fragment (p single x V hi/lo)
#pragma unroll
            for (int ksl = 0; ksl < 2; ksl++) {
                int mr = half*32 + ksl*16 + qc2;
#pragma unroll
                for (int nf = 0; nf < 8; nf++) {
                    int dc = nf*8 + qr;
                    uint32_t bvh[2], bvl[2];
                    bvh[0] = *(const uint32_t*)&Vth[buf][dc][mr];
                    bvh[1] = *(const uint32_t*)&Vth[buf][dc][mr+8];
                    bvl[0] = *(const uint32_t*)&Vtl[buf][dc][mr];
                    bvl[1] = *(const uint32_t*)&Vtl[buf][dc][mr+8];
                    mma_f16(hid[nf], pa[ksl], bvh);
                    mma_f16(hid[nf], pa[ksl], bvl);
                }
            }
        }
    }

    // rowsum reduce across the quad, write inverse, write normalized hidden
    rs_lo += __shfl_xor_sync(0xffffffffu, rs_lo, 1);
    rs_lo += __shfl_xor_sync(0xffffffffu, rs_lo, 2);
    rs_hi += __shfl_xor_sync(0xffffffffu, rs_hi, 1);
    rs_hi += __shfl_xor_sync(0xffffffffu, rs_hi, 2);
    float inv_lo = 1.0f / rs_lo;
    float inv_hi = 1.0f / rs_hi;
    if ((lane & 3) == 0) {
        g_inv[(size_t)bh*Nn + n_lo]     = inv_lo;
        g_inv[(size_t)bh*Nn + n_lo + 8] = inv_hi;
    }
#pragma unroll
    for (int nf = 0; nf < 8; nf++) {
        int d = nf*8 + qc2;
        size_t o_lo = ((size_t)b*Nn + n_lo)*Cc + h*64 + d;
        size_t o_hi = o_lo + (size_t)8*Cc;
        *(float2*)&out_hidden[o_lo] = make_float2(hid[nf][0]*inv_lo, hid[nf][1]*inv_lo);
        *(float2*)&out_hidden[o_hi] = make_float2(hid[nf][2]*inv_hi, hid[nf][3]*inv_hi);
    }
}

// ---------------- K3: normalize attn in place (MLP=4) ----------------
// grid: 32768 x 256; each thread scales 4 strided float4s.
__global__ __launch_bounds__(256) void norm_kernel(float4* __restrict__ attn4) {
    int base = blockIdx.x * 1024 + threadIdx.x;
    float4 v0 = attn4[base];
    float4 v1 = attn4[base + 256];
    float4 v2 = attn4[base + 512];
    float4 v3 = attn4[base + 768];
    float i0 = g_inv[(base)       >> 9];
    float i1 = g_inv[(base + 256) >> 9];
    float i2 = g_inv[(base + 512) >> 9];
    float i3 = g_inv[(base + 768) >> 9];
    v0.x *= i0; v0.y *= i0; v0.z *= i0; v0.w *= i0;
    v1.x *= i1; v1.y *= i1; v1.z *= i1; v1.w *= i1;
    v2.x *= i2; v2.y *= i2; v2.z *= i2; v2.w *= i2;
    v3.x *= i3; v3.y *= i3; v3.z *= i3; v3.w *= i3;
    attn4[base]       = v0;
    attn4[base + 256] = v1;
    attn4[base + 512] = v2;
    attn4[base + 768] = v3;
}

// ---------------- launch ----------------
extern "C" void kernel_launch(void* const* d_in, const int* in_sizes, int n_in,
                              void* d_out, int out_size) {
    const float* xq    = (const float*)d_in[0];
    const float* xk    = (const float*)d_in[1];
    const float* xv    = (const float*)d_in[2];
    const float* kw    = (const float*)d_in[3];
    const int*   kmask = (const int*)d_in[4];
    const float* af    = (const float*)d_in[5];
    const int*   amask = (const int*)d_in[6];
    const float* Wq    = (const float*)d_in[7];
    const float* bq    = (const float*)d_in[8];
    const float* Wk    = (const float*)d_in[9];
    const float* bk    = (const float*)d_in[10];
    const float* Wv    = (const float*)d_in[11];
    const float* bv    = (const float*)d_in[12];

    float* out_hidden = (float*)d_out;
    float* out_attn   = out_hidden + (size_t)Bb*Nn*Cc;

    const int attn_smem = 3*NSTG*TILE_B + NSTG*64*(int)sizeof(int);   // 55,808 B
    cudaFuncSetAttribute(attn_kernel, cudaFuncAttributeMaxDynamicSharedMemorySize, attn_smem);

    proj_kernel<<<dim3(64, 8, 3), 256>>>(xq, xk, xv, Wq, bq, Wk, bk, Wv, bv, kw);
    attn_kernel<<<dim3(8, 32, 4), 128, attn_smem>>>(kmask, af, amask, out_hidden, out_attn);
    norm_kernel<<<32768, 256>>>((float4*)out_attn);
}